// round 9
// baseline (speedup 1.0000x reference)
#include <cuda_runtime.h>
#include <cuda_fp16.h>
#include <math.h>
#include <stdint.h>

// Problem constants
static constexpr int BB  = 4;
static constexpr int TT  = 4096;
static constexpr int DD  = 1024;
static constexpr int HH  = 16;
static constexpr int DKK = 64;
static constexpr int MT  = BB * TT;      // 16384 tokens
static constexpr int KK  = DD;           // fp16 GEMM K = 1024
static constexpr int BKC = 32;           // K-chunk (fp16 elems)
static constexpr int NCHUNK = KK / BKC;  // 32
#define EPSV 1e-6f

// GEMM SMEM geometry: rows padded to 40 fp16 (80 B) for conflict-free ldmatrix
static constexpr int ROWB  = 80;
static constexpr int TILEB = 128 * ROWB;
static constexpr int STGB  = 2 * TILEB;
static constexpr int NSTG  = 4;
static constexpr int SMEM_GEMM = NSTG * STGB; // 81920 B

// kv/attn smem row stride for 64-wide fp16 tiles: 128B data + 16B pad
static constexpr int RS64 = 144;

// ---------------------------------------------------------------------------
// Scratch (device globals — no allocation allowed)
// ---------------------------------------------------------------------------
__device__ __half g_xs[(size_t)MT * KK];      // x fp16
__device__ __half g_as[(size_t)MT * KK];      // attn out fp16
__device__ __half g_wqkv[3 * DD * KK];        // packed Wq|Wk|Wv fp16
__device__ __half g_wos[DD * KK];             // Wo fp16
__device__ __half g_q16[(size_t)MT * DD];
__device__ __half g_k16[(size_t)MT * DD];
__device__ __half g_v16[(size_t)MT * DD];
__device__ float  g_kv[BB * HH * DKK * DKK];
__device__ float  g_ksum[BB * HH * DKK];

__device__ __forceinline__ float phi_act(float x) {
    return x > 0.0f ? x + 1.0f : expf(x);
}

// ---------------------------------------------------------------------------
// PTX helpers (baseline sm_80+ features only)
// ---------------------------------------------------------------------------
__device__ __forceinline__ uint32_t smem_u32(const void* p) {
    uint32_t a;
    asm("{ .reg .u64 t; cvta.to.shared.u64 t, %1; cvt.u32.u64 %0, t; }"
        : "=r"(a) : "l"(p));
    return a;
}

#define CP_ASYNC16(sm, gp) \
    asm volatile("cp.async.cg.shared.global [%0], [%1], 16;" :: "r"(sm), "l"(gp))
#define CP_COMMIT() asm volatile("cp.async.commit_group;")
template <int N> __device__ __forceinline__ void cp_wait() {
    asm volatile("cp.async.wait_group %0;" :: "n"(N));
}

__device__ __forceinline__ void ldsm_x4(uint32_t* r, uint32_t addr) {
    asm volatile("ldmatrix.sync.aligned.m8n8.x4.shared.b16 {%0,%1,%2,%3}, [%4];"
                 : "=r"(r[0]), "=r"(r[1]), "=r"(r[2]), "=r"(r[3]) : "r"(addr));
}
__device__ __forceinline__ void ldsm_x4_t(uint32_t* r, uint32_t addr) {
    asm volatile("ldmatrix.sync.aligned.m8n8.x4.trans.shared.b16 {%0,%1,%2,%3}, [%4];"
                 : "=r"(r[0]), "=r"(r[1]), "=r"(r[2]), "=r"(r[3]) : "r"(addr));
}

__device__ __forceinline__ void mma_fp16(float* c, const uint32_t* a,
                                         uint32_t b0, uint32_t b1) {
    asm volatile(
        "mma.sync.aligned.m16n8k16.row.col.f32.f16.f16.f32 "
        "{%0,%1,%2,%3}, {%4,%5,%6,%7}, {%8,%9}, {%0,%1,%2,%3};"
        : "+f"(c[0]), "+f"(c[1]), "+f"(c[2]), "+f"(c[3])
        : "r"(a[0]), "r"(a[1]), "r"(a[2]), "r"(a[3]), "r"(b0), "r"(b1));
}

// ---------------------------------------------------------------------------
// GEMM mainloop core (at the HMMA issue floor)
// ---------------------------------------------------------------------------
struct GemmCore {
    uint32_t tiles, sw0, a_off, b_off;
    const char *Ag, *Wg;
    float acc[4][4][4];

    __device__ __forceinline__ void init(uint32_t tiles_, int tid,
                                         const __half* A, const __half* W,
                                         int bm, int bn) {
        tiles = tiles_;
        const int wid  = tid >> 5, lane = tid & 31;
        const int wm   = wid >> 2, wn = wid & 3;
        const int lrow = tid >> 1;
        const int lc16 = (tid & 1) * 2;
        sw0 = (uint32_t)lrow * ROWB + lc16 * 16;
        Ag = (const char*)(A + (size_t)(bm * 128 + lrow) * KK) + lc16 * 16;
        Wg = (const char*)(W + (size_t)(bn * 128 + lrow) * KK) + lc16 * 16;
        a_off = (uint32_t)(wm * 64 + (lane & 15)) * ROWB + (lane >> 4) * 16;
        b_off = TILEB + (uint32_t)(wn * 32 + (lane & 15)) * ROWB + (lane >> 4) * 16;
        #pragma unroll
        for (int i = 0; i < 4; i++)
            #pragma unroll
            for (int j = 0; j < 4; j++)
                #pragma unroll
                for (int r = 0; r < 4; r++) acc[i][j][r] = 0.0f;
    }

    __device__ __forceinline__ void load_chunk(int kc) {
        const uint32_t st = tiles + (kc & (NSTG - 1)) * STGB;
        const char* ga = Ag + (size_t)kc * (BKC * 2);
        const char* gb = Wg + (size_t)kc * (BKC * 2);
        CP_ASYNC16(st + sw0,              ga);
        CP_ASYNC16(st + sw0 + 16,         ga + 16);
        CP_ASYNC16(st + TILEB + sw0,      gb);
        CP_ASYNC16(st + TILEB + sw0 + 16, gb + 16);
        CP_COMMIT();
    }

    __device__ __forceinline__ void run() {
        load_chunk(0); load_chunk(1); load_chunk(2);
        #pragma unroll 1
        for (int kc = 0; kc < NCHUNK; kc++) {
            if (kc < NCHUNK - 2)       cp_wait<2>();
            else if (kc == NCHUNK - 2) cp_wait<1>();
            else                       cp_wait<0>();
            __syncthreads();
            if (kc + 3 < NCHUNK) load_chunk(kc + 3);

            const uint32_t st = tiles + (kc & (NSTG - 1)) * STGB;
            #pragma unroll
            for (int ks = 0; ks < 2; ks++) {
                const uint32_t kb = ks * 32;
                uint32_t a[4][4], b[2][4];
                #pragma unroll
                for (int mf = 0; mf < 4; mf++)
                    ldsm_x4(a[mf], st + a_off + mf * (16 * ROWB) + kb);
                #pragma unroll
                for (int nf2 = 0; nf2 < 2; nf2++)
                    ldsm_x4(b[nf2], st + b_off + nf2 * (16 * ROWB) + kb);
                #pragma unroll
                for (int mf = 0; mf < 4; mf++) {
                    #pragma unroll
                    for (int nf = 0; nf < 4; nf++)
                        mma_fp16(acc[mf][nf], a[mf],
                                 b[nf >> 1][nf & 1], b[nf >> 1][(nf & 1) + 2]);
                }
            }
        }
    }
};

// ---------------------------------------------------------------------------
// Fused QKV GEMM -> fp16 outputs (seg 0=Q+phi, 1=K+phi, 2=V); grid (24, 128)
// ---------------------------------------------------------------------------
__global__ void __launch_bounds__(256, 2) gemm_qkv(
    const __half* __restrict__ A, const __half* __restrict__ Wqkv,
    const float* __restrict__ bq, const float* __restrict__ bk,
    const float* __restrict__ bv,
    __half* __restrict__ Cq, __half* __restrict__ Ck, __half* __restrict__ Cv)
{
    extern __shared__ char smraw[];
    const int tid = threadIdx.x;
    const int wid = tid >> 5, lane = tid & 31;
    const int wm  = wid >> 2, wn = wid & 3;
    const int bm  = blockIdx.y, bn = blockIdx.x;

    const int seg = bn >> 3;
    const float* bias = seg == 0 ? bq : (seg == 1 ? bk : bv);
    __half* C = seg == 0 ? Cq : (seg == 1 ? Ck : Cv);
    const bool act = seg < 2;

    GemmCore g;
    g.init(smem_u32(smraw), tid, A, Wqkv, bm, bn);
    g.run();

    #pragma unroll
    for (int mf = 0; mf < 4; mf++) {
        const int m0 = bm * 128 + wm * 64 + mf * 16 + (lane >> 2);
        #pragma unroll
        for (int nf = 0; nf < 4; nf++) {
            const int nc = (bn & 7) * 128 + wn * 32 + nf * 8 + (lane & 3) * 2;
            const float b0 = __ldg(bias + nc), b1 = __ldg(bias + nc + 1);
            float l0 = g.acc[mf][nf][0] + b0, l1 = g.acc[mf][nf][1] + b1;
            float h0 = g.acc[mf][nf][2] + b0, h1 = g.acc[mf][nf][3] + b1;
            if (act) { l0 = phi_act(l0); l1 = phi_act(l1);
                       h0 = phi_act(h0); h1 = phi_act(h1); }
            *(__half2*)(C + (size_t)m0 * 1024 + nc) =
                __half2(__float2half(l0), __float2half(l1));
            *(__half2*)(C + (size_t)(m0 + 8) * 1024 + nc) =
                __half2(__float2half(h0), __float2half(h1));
        }
    }
}

// ---------------------------------------------------------------------------
// Output GEMM: out = attn_fp16 @ Wo^T + bo  -> fp32
// ---------------------------------------------------------------------------
__global__ void __launch_bounds__(256, 2) gemm_out(
    const __half* __restrict__ A, const __half* __restrict__ W,
    const float* __restrict__ bias, float* __restrict__ C)
{
    extern __shared__ char smraw[];
    const int tid = threadIdx.x;
    const int wid = tid >> 5, lane = tid & 31;
    const int wm  = wid >> 2, wn = wid & 3;
    const int bm  = blockIdx.y, bn = blockIdx.x;

    GemmCore g;
    g.init(smem_u32(smraw), tid, A, W, bm, bn);
    g.run();

    #pragma unroll
    for (int mf = 0; mf < 4; mf++) {
        const int m0 = bm * 128 + wm * 64 + mf * 16 + (lane >> 2);
        #pragma unroll
        for (int nf = 0; nf < 4; nf++) {
            const int nc = bn * 128 + wn * 32 + nf * 8 + (lane & 3) * 2;
            const float b0 = __ldg(bias + nc), b1 = __ldg(bias + nc + 1);
            float2 lo, hi;
            lo.x = g.acc[mf][nf][0] + b0; lo.y = g.acc[mf][nf][1] + b1;
            hi.x = g.acc[mf][nf][2] + b0; hi.y = g.acc[mf][nf][3] + b1;
            *(float2*)(C + (size_t)m0 * 1024 + nc)       = lo;
            *(float2*)(C + (size_t)(m0 + 8) * 1024 + nc) = hi;
        }
    }
}

// ---------------------------------------------------------------------------
// fp32 -> fp16 convert, [rows, 1024]
// ---------------------------------------------------------------------------
__global__ __launch_bounds__(256) void conv_fp16(
    const float* __restrict__ src, __half* __restrict__ dst)
{
    const int m = blockIdx.x;
    const int c = threadIdx.x * 4;
    float4 v = *(const float4*)(src + (size_t)m * 1024 + c);
    __half2* d = (__half2*)(dst + (size_t)m * 1024 + c);
    d[0] = __half2(__float2half(v.x), __float2half(v.y));
    d[1] = __half2(__float2half(v.z), __float2half(v.w));
}

// ---------------------------------------------------------------------------
// KV summary (HMMA): per (b,h,split): kv[64,64] += k^T @ v over 512 t.
// grid (64, 8), 8 warps: 2 (m=dk) x 4 (n=dm).
// ---------------------------------------------------------------------------
__global__ __launch_bounds__(256) void kv_hmma(
    const __half* __restrict__ k16, const __half* __restrict__ v16)
{
    __shared__ __align__(16) char sm[4 * 2 * 32 * RS64];
    const uint32_t smb = smem_u32(sm);
    const int tid = threadIdx.x, lane = tid & 31, wid = tid >> 5;
    const int wm = wid >> 2, wn = wid & 3;
    const int bh = blockIdx.x, b = bh >> 4, h = bh & 15;
    const int t0 = blockIdx.y * 512;
    static constexpr int NCH = 16;
    static constexpr int STG = 2 * 32 * RS64;

    const int lrow = tid >> 3, lseg = tid & 7;
    const __half* gk = k16 + (size_t)(b * TT + t0 + lrow) * 1024 + h * 64 + lseg * 8;
    const __half* gv = v16 + (size_t)(b * TT + t0 + lrow) * 1024 + h * 64 + lseg * 8;
    const uint32_t sdst = (uint32_t)lrow * RS64 + lseg * 16;

    auto load_chunk = [&](int ch) {
        const uint32_t st = smb + (ch & 3) * STG;
        const size_t go = (size_t)ch * 32 * 1024;
        CP_ASYNC16(st + sdst,             gk + go);
        CP_ASYNC16(st + 32 * RS64 + sdst, gv + go);
        CP_COMMIT();
    };

    const uint32_t trow = (lane & 7) + ((lane >> 4) & 1) * 8;
    const uint32_t tcol = ((lane >> 3) & 1) * 8;
    const uint32_t a_base = trow * RS64 + (wm * 32 + tcol) * 2;
    const uint32_t b_base = 32 * RS64 + trow * RS64 + (wn * 16 + tcol) * 2;

    float acc[2][2][4];
    #pragma unroll
    for (int i = 0; i < 2; i++)
        #pragma unroll
        for (int j = 0; j < 2; j++)
            #pragma unroll
            for (int r = 0; r < 4; r++) acc[i][j][r] = 0.0f;
    float ksacc = 0.0f;

    load_chunk(0); load_chunk(1); load_chunk(2);

    #pragma unroll 1
    for (int ch = 0; ch < NCH; ch++) {
        if (ch < NCH - 2)       cp_wait<2>();
        else if (ch == NCH - 2) cp_wait<1>();
        else                    cp_wait<0>();
        __syncthreads();
        if (ch + 3 < NCH) load_chunk(ch + 3);

        const uint32_t st = smb + (ch & 3) * STG;
        #pragma unroll
        for (int ks = 0; ks < 2; ks++) {
            const uint32_t ko = ks * 16 * RS64;
            uint32_t a[2][4], bfr[4];
            ldsm_x4_t(a[0], st + a_base + ko);
            ldsm_x4_t(a[1], st + a_base + ko + 16 * 2);
            ldsm_x4_t(bfr,  st + b_base + ko);
            #pragma unroll
            for (int mf = 0; mf < 2; mf++)
                #pragma unroll
                for (int nf = 0; nf < 2; nf++)
                    mma_fp16(acc[mf][nf], a[mf], bfr[nf], bfr[nf + 2]);
        }
        if (tid < 64) {
            const __half* kc = (const __half*)(sm + (ch & 3) * STG);
            #pragma unroll
            for (int r = 0; r < 32; r++)
                ksacc += __half2float(*(const __half*)
                    ((const char*)kc + r * RS64 + tid * 2));
        }
    }

    float* kvb = g_kv + (size_t)bh * DKK * DKK;
    #pragma unroll
    for (int mf = 0; mf < 2; mf++) {
        const int row = wm * 32 + mf * 16 + (lane >> 2);
        #pragma unroll
        for (int nf = 0; nf < 2; nf++) {
            const int col = wn * 16 + nf * 8 + (lane & 3) * 2;
            atomicAdd(&kvb[row * 64 + col],           acc[mf][nf][0]);
            atomicAdd(&kvb[row * 64 + col + 1],       acc[mf][nf][1]);
            atomicAdd(&kvb[(row + 8) * 64 + col],     acc[mf][nf][2]);
            atomicAdd(&kvb[(row + 8) * 64 + col + 1], acc[mf][nf][3]);
        }
    }
    if (tid < 64) atomicAdd(&g_ksum[bh * 64 + tid], ksacc);
}

// ---------------------------------------------------------------------------
// Attention apply (HMMA) with fused kv fixup:
//   - loads f32 kv[64,64] per (b,h), converts+transposes to fp16 in smem
//   - kse = ksum + eps computed in-kernel
//   - out[t,dm] = z[t] * (q[t,:] @ kv[:,dm]) in fp16
// grid (64, 32), 8 warps: 4 (m=t) x 2 (n=dm).
// ---------------------------------------------------------------------------
__global__ __launch_bounds__(256) void attn_hmma(
    const __half* __restrict__ q16, __half* __restrict__ out)
{
    __shared__ __align__(16) char smq[128 * RS64];     // 18432 B
    __shared__ __align__(16) float smkv32[64 * 64];    // 16384 B
    __shared__ __align__(16) char smkv[64 * RS64];     // 9216 B
    __shared__ float zs[128];
    __shared__ float kse[64];

    const uint32_t sq = smem_u32(smq), skv = smem_u32(smkv);
    const int tid = threadIdx.x, lane = tid & 31, wid = tid >> 5;
    const int wm = wid >> 1, wn = wid & 1;
    const int bh = blockIdx.x, b = bh >> 4, h = bh & 15;
    const int t0 = blockIdx.y * 128;

    // async loads: q tile (128x8 segs) + f32 kv (1024 segs of 16B)
    {
        const __half* gq = q16 + (size_t)(b * TT + t0) * 1024 + h * 64;
        #pragma unroll
        for (int i = 0; i < 4; i++) {
            const int s = i * 256 + tid;
            const int r = s >> 3, c = s & 7;
            CP_ASYNC16(sq + r * RS64 + c * 16, gq + (size_t)r * 1024 + c * 8);
        }
        const float* gkv = g_kv + (size_t)bh * 4096;
        const uint32_t skv32 = smem_u32(smkv32);
        #pragma unroll
        for (int i = 0; i < 4; i++) {
            const int s = i * 256 + tid;
            CP_ASYNC16(skv32 + s * 16, gkv + s * 4);
        }
        CP_COMMIT();
    }
    if (tid < 64) kse[tid] = g_ksum[bh * 64 + tid] + EPSV;
    cp_wait<0>();
    __syncthreads();

    // convert f32 kv[dk][dm] -> fp16 kvT[dm][dk] in smem (16 elems/thread)
    #pragma unroll
    for (int i = 0; i < 16; i++) {
        const int s = i * 256 + tid;       // s = dm*64 + dk
        const int dm = s >> 6, dk = s & 63;
        *(__half*)(smkv + dm * RS64 + dk * 2) =
            __float2half(smkv32[dk * 64 + dm]);
    }
    __syncthreads();

    if (tid < 128) {
        float s = EPSV;
        const char* qrow = smq + tid * RS64;
        #pragma unroll
        for (int d = 0; d < 64; d++)
            s = fmaf(__half2float(*(const __half*)(qrow + d * 2)), kse[d], s);
        zs[tid] = 1.0f / s;
    }
    __syncthreads();

    const uint32_t a_base = (uint32_t)(wm * 32 + (lane & 15)) * RS64 + (lane >> 4) * 16;
    const uint32_t b_base = (uint32_t)(wn * 32 + (lane & 15)) * RS64 + (lane >> 4) * 16;

    float acc[2][4][4];
    #pragma unroll
    for (int i = 0; i < 2; i++)
        #pragma unroll
        for (int j = 0; j < 4; j++)
            #pragma unroll
            for (int r = 0; r < 4; r++) acc[i][j][r] = 0.0f;

    #pragma unroll
    for (int ks = 0; ks < 4; ks++) {
        const uint32_t ko = ks * 32;
        uint32_t a[2][4], bl[2][4];
        ldsm_x4(a[0], sq + a_base + ko);
        ldsm_x4(a[1], sq + a_base + 16 * RS64 + ko);
        ldsm_x4(bl[0], skv + b_base + ko);
        ldsm_x4(bl[1], skv + b_base + 16 * RS64 + ko);
        #pragma unroll
        for (int mf = 0; mf < 2; mf++)
            #pragma unroll
            for (int nf = 0; nf < 4; nf++)
                mma_fp16(acc[mf][nf], a[mf],
                         bl[nf >> 1][nf & 1], bl[nf >> 1][(nf & 1) + 2]);
    }

    #pragma unroll
    for (int mf = 0; mf < 2; mf++) {
        const int row = wm * 32 + mf * 16 + (lane >> 2);
        const float z0 = zs[row], z1 = zs[row + 8];
        #pragma unroll
        for (int nf = 0; nf < 4; nf++) {
            const int col = wn * 32 + nf * 8 + (lane & 3) * 2;
            __half2* o0 = (__half2*)(out + (size_t)(b * TT + t0 + row) * 1024 + h * 64 + col);
            __half2* o1 = (__half2*)(out + (size_t)(b * TT + t0 + row + 8) * 1024 + h * 64 + col);
            *o0 = __half2(__float2half(acc[mf][nf][0] * z0),
                          __float2half(acc[mf][nf][1] * z0));
            *o1 = __half2(__float2half(acc[mf][nf][2] * z1),
                          __float2half(acc[mf][nf][3] * z1));
        }
    }
}

// ---------------------------------------------------------------------------
extern "C" void kernel_launch(void* const* d_in, const int* in_sizes, int n_in,
                              void* d_out, int out_size)
{
    const float* x  = (const float*)d_in[0];
    const float* Wq = (const float*)d_in[1];
    const float* bq = (const float*)d_in[2];
    const float* Wk = (const float*)d_in[3];
    const float* bk = (const float*)d_in[4];
    const float* Wv = (const float*)d_in[5];
    const float* bv = (const float*)d_in[6];
    const float* Wo = (const float*)d_in[7];
    const float* bo = (const float*)d_in[8];
    float* out = (float*)d_out;

    __half *xs, *as, *wqkv, *wos, *qp, *kp, *vp;
    float *kvp, *ksp;
    cudaGetSymbolAddress((void**)&xs,   g_xs);
    cudaGetSymbolAddress((void**)&as,   g_as);
    cudaGetSymbolAddress((void**)&wqkv, g_wqkv);
    cudaGetSymbolAddress((void**)&wos,  g_wos);
    cudaGetSymbolAddress((void**)&qp,   g_q16);
    cudaGetSymbolAddress((void**)&kp,   g_k16);
    cudaGetSymbolAddress((void**)&vp,   g_v16);
    cudaGetSymbolAddress((void**)&kvp,  g_kv);
    cudaGetSymbolAddress((void**)&ksp,  g_ksum);

    cudaFuncSetAttribute(gemm_qkv, cudaFuncAttributeMaxDynamicSharedMemorySize, SMEM_GEMM);
    cudaFuncSetAttribute(gemm_out, cudaFuncAttributeMaxDynamicSharedMemorySize, SMEM_GEMM);

    // Launch order: 5 convs, then gemm_qkv as the 6th node (ncu -s 5 -c 1
    // captures it). Memsets moved after gemm_qkv (still before kv_hmma).
    conv_fp16<<<MT, 256>>>(x, xs);
    conv_fp16<<<DD, 256>>>(Wq, wqkv);
    conv_fp16<<<DD, 256>>>(Wk, wqkv + (size_t)DD * KK);
    conv_fp16<<<DD, 256>>>(Wv, wqkv + (size_t)2 * DD * KK);
    conv_fp16<<<DD, 256>>>(Wo, wos);

    gemm_qkv<<<dim3(24, MT / 128), 256, SMEM_GEMM>>>(
        xs, wqkv, bq, bk, bv, qp, kp, vp);

    cudaMemsetAsync(kvp, 0, sizeof(float) * BB * HH * DKK * DKK);
    cudaMemsetAsync(ksp, 0, sizeof(float) * BB * HH * DKK);

    kv_hmma<<<dim3(BB * HH, 8), 256>>>(kp, vp);
    attn_hmma<<<dim3(BB * HH, TT / 128), 256>>>(qp, as);

    gemm_out<<<dim3(DD / 128, MT / 128), 256, SMEM_GEMM>>>(as, wos, bo, out);
}

// round 10
// speedup vs baseline: 1.0539x; 1.0539x over previous
#include <cuda_runtime.h>
#include <cuda_fp16.h>
#include <math.h>
#include <stdint.h>

// Problem constants
static constexpr int BB  = 4;
static constexpr int TT  = 4096;
static constexpr int DD  = 1024;
static constexpr int HH  = 16;
static constexpr int DKK = 64;
static constexpr int MT  = BB * TT;      // 16384 tokens
static constexpr int KK  = DD;           // fp16 GEMM K = 1024
static constexpr int BKC = 32;           // K-chunk (fp16 elems)
static constexpr int NCHUNK = KK / BKC;  // 32
static constexpr int NSPL = 8;           // kv t-splits
#define EPSV 1e-6f

// GEMM SMEM geometry: rows padded to 40 fp16 (80 B) for conflict-free ldmatrix
static constexpr int ROWB  = 80;
static constexpr int TILEB = 128 * ROWB;
static constexpr int STGB  = 2 * TILEB;
static constexpr int NSTG  = 4;
static constexpr int SMEM_GEMM = NSTG * STGB; // 81920 B

// kv/attn smem row stride for 64-wide fp16 tiles: 128B data + 16B pad
static constexpr int RS64 = 144;

// ---------------------------------------------------------------------------
// Scratch (device globals — no allocation allowed)
// ---------------------------------------------------------------------------
__device__ __half g_xs[(size_t)MT * KK];      // x fp16
__device__ __half g_as[(size_t)MT * KK];      // attn out fp16
__device__ __half g_wqkv[3 * DD * KK];        // packed Wq|Wk|Wv fp16
__device__ __half g_wos[DD * KK];             // Wo fp16
__device__ __half g_q16[(size_t)MT * DD];
__device__ __half g_k16[(size_t)MT * DD];
__device__ __half g_v16[(size_t)MT * DD];
__device__ float  g_kvp[BB * HH * NSPL * DKK * DKK];  // kv partials (8 MB)
__device__ float  g_ksp[BB * HH * NSPL * DKK];        // ksum partials
__device__ __half g_kvT[BB * HH * DKK * DKK];         // fp16 kv^T
__device__ float  g_kse[BB * HH * DKK];               // ksum + eps

__device__ __forceinline__ float phi_act(float x) {
    return x > 0.0f ? x + 1.0f : expf(x);
}

// ---------------------------------------------------------------------------
// PTX helpers (baseline sm_80+ features only)
// ---------------------------------------------------------------------------
__device__ __forceinline__ uint32_t smem_u32(const void* p) {
    uint32_t a;
    asm("{ .reg .u64 t; cvta.to.shared.u64 t, %1; cvt.u32.u64 %0, t; }"
        : "=r"(a) : "l"(p));
    return a;
}

#define CP_ASYNC16(sm, gp) \
    asm volatile("cp.async.cg.shared.global [%0], [%1], 16;" :: "r"(sm), "l"(gp))
#define CP_COMMIT() asm volatile("cp.async.commit_group;")
template <int N> __device__ __forceinline__ void cp_wait() {
    asm volatile("cp.async.wait_group %0;" :: "n"(N));
}

__device__ __forceinline__ void ldsm_x4(uint32_t* r, uint32_t addr) {
    asm volatile("ldmatrix.sync.aligned.m8n8.x4.shared.b16 {%0,%1,%2,%3}, [%4];"
                 : "=r"(r[0]), "=r"(r[1]), "=r"(r[2]), "=r"(r[3]) : "r"(addr));
}
__device__ __forceinline__ void ldsm_x4_t(uint32_t* r, uint32_t addr) {
    asm volatile("ldmatrix.sync.aligned.m8n8.x4.trans.shared.b16 {%0,%1,%2,%3}, [%4];"
                 : "=r"(r[0]), "=r"(r[1]), "=r"(r[2]), "=r"(r[3]) : "r"(addr));
}

__device__ __forceinline__ void mma_fp16(float* c, const uint32_t* a,
                                         uint32_t b0, uint32_t b1) {
    asm volatile(
        "mma.sync.aligned.m16n8k16.row.col.f32.f16.f16.f32 "
        "{%0,%1,%2,%3}, {%4,%5,%6,%7}, {%8,%9}, {%0,%1,%2,%3};"
        : "+f"(c[0]), "+f"(c[1]), "+f"(c[2]), "+f"(c[3])
        : "r"(a[0]), "r"(a[1]), "r"(a[2]), "r"(a[3]), "r"(b0), "r"(b1));
}

// ---------------------------------------------------------------------------
// GEMM mainloop core (at the HMMA issue floor)
// ---------------------------------------------------------------------------
struct GemmCore {
    uint32_t tiles, sw0, a_off, b_off;
    const char *Ag, *Wg;
    float acc[4][4][4];

    __device__ __forceinline__ void init(uint32_t tiles_, int tid,
                                         const __half* A, const __half* W,
                                         int bm, int bn) {
        tiles = tiles_;
        const int wid  = tid >> 5, lane = tid & 31;
        const int wm   = wid >> 2, wn = wid & 3;
        const int lrow = tid >> 1;
        const int lc16 = (tid & 1) * 2;
        sw0 = (uint32_t)lrow * ROWB + lc16 * 16;
        Ag = (const char*)(A + (size_t)(bm * 128 + lrow) * KK) + lc16 * 16;
        Wg = (const char*)(W + (size_t)(bn * 128 + lrow) * KK) + lc16 * 16;
        a_off = (uint32_t)(wm * 64 + (lane & 15)) * ROWB + (lane >> 4) * 16;
        b_off = TILEB + (uint32_t)(wn * 32 + (lane & 15)) * ROWB + (lane >> 4) * 16;
        #pragma unroll
        for (int i = 0; i < 4; i++)
            #pragma unroll
            for (int j = 0; j < 4; j++)
                #pragma unroll
                for (int r = 0; r < 4; r++) acc[i][j][r] = 0.0f;
    }

    __device__ __forceinline__ void load_chunk(int kc) {
        const uint32_t st = tiles + (kc & (NSTG - 1)) * STGB;
        const char* ga = Ag + (size_t)kc * (BKC * 2);
        const char* gb = Wg + (size_t)kc * (BKC * 2);
        CP_ASYNC16(st + sw0,              ga);
        CP_ASYNC16(st + sw0 + 16,         ga + 16);
        CP_ASYNC16(st + TILEB + sw0,      gb);
        CP_ASYNC16(st + TILEB + sw0 + 16, gb + 16);
        CP_COMMIT();
    }

    __device__ __forceinline__ void run() {
        load_chunk(0); load_chunk(1); load_chunk(2);
        #pragma unroll 1
        for (int kc = 0; kc < NCHUNK; kc++) {
            if (kc < NCHUNK - 2)       cp_wait<2>();
            else if (kc == NCHUNK - 2) cp_wait<1>();
            else                       cp_wait<0>();
            __syncthreads();
            if (kc + 3 < NCHUNK) load_chunk(kc + 3);

            const uint32_t st = tiles + (kc & (NSTG - 1)) * STGB;
            #pragma unroll
            for (int ks = 0; ks < 2; ks++) {
                const uint32_t kb = ks * 32;
                uint32_t a[4][4], b[2][4];
                #pragma unroll
                for (int mf = 0; mf < 4; mf++)
                    ldsm_x4(a[mf], st + a_off + mf * (16 * ROWB) + kb);
                #pragma unroll
                for (int nf2 = 0; nf2 < 2; nf2++)
                    ldsm_x4(b[nf2], st + b_off + nf2 * (16 * ROWB) + kb);
                #pragma unroll
                for (int mf = 0; mf < 4; mf++) {
                    #pragma unroll
                    for (int nf = 0; nf < 4; nf++)
                        mma_fp16(acc[mf][nf], a[mf],
                                 b[nf >> 1][nf & 1], b[nf >> 1][(nf & 1) + 2]);
                }
            }
        }
    }
};

// ---------------------------------------------------------------------------
// Fused QKV GEMM -> fp16 outputs (seg 0=Q+phi, 1=K+phi, 2=V); grid (24, 128)
// ---------------------------------------------------------------------------
__global__ void __launch_bounds__(256, 2) gemm_qkv(
    const __half* __restrict__ A, const __half* __restrict__ Wqkv,
    const float* __restrict__ bq, const float* __restrict__ bk,
    const float* __restrict__ bv,
    __half* __restrict__ Cq, __half* __restrict__ Ck, __half* __restrict__ Cv)
{
    extern __shared__ char smraw[];
    const int tid = threadIdx.x;
    const int wid = tid >> 5, lane = tid & 31;
    const int wm  = wid >> 2, wn = wid & 3;
    const int bm  = blockIdx.y, bn = blockIdx.x;

    const int seg = bn >> 3;
    const float* bias = seg == 0 ? bq : (seg == 1 ? bk : bv);
    __half* C = seg == 0 ? Cq : (seg == 1 ? Ck : Cv);
    const bool act = seg < 2;

    GemmCore g;
    g.init(smem_u32(smraw), tid, A, Wqkv, bm, bn);
    g.run();

    #pragma unroll
    for (int mf = 0; mf < 4; mf++) {
        const int m0 = bm * 128 + wm * 64 + mf * 16 + (lane >> 2);
        #pragma unroll
        for (int nf = 0; nf < 4; nf++) {
            const int nc = (bn & 7) * 128 + wn * 32 + nf * 8 + (lane & 3) * 2;
            const float b0 = __ldg(bias + nc), b1 = __ldg(bias + nc + 1);
            float l0 = g.acc[mf][nf][0] + b0, l1 = g.acc[mf][nf][1] + b1;
            float h0 = g.acc[mf][nf][2] + b0, h1 = g.acc[mf][nf][3] + b1;
            if (act) { l0 = phi_act(l0); l1 = phi_act(l1);
                       h0 = phi_act(h0); h1 = phi_act(h1); }
            *(__half2*)(C + (size_t)m0 * 1024 + nc) =
                __half2(__float2half(l0), __float2half(l1));
            *(__half2*)(C + (size_t)(m0 + 8) * 1024 + nc) =
                __half2(__float2half(h0), __float2half(h1));
        }
    }
}

// ---------------------------------------------------------------------------
// Output GEMM: out = attn_fp16 @ Wo^T + bo  -> fp32
// ---------------------------------------------------------------------------
__global__ void __launch_bounds__(256, 2) gemm_out(
    const __half* __restrict__ A, const __half* __restrict__ W,
    const float* __restrict__ bias, float* __restrict__ C)
{
    extern __shared__ char smraw[];
    const int tid = threadIdx.x;
    const int wid = tid >> 5, lane = tid & 31;
    const int wm  = wid >> 2, wn = wid & 3;
    const int bm  = blockIdx.y, bn = blockIdx.x;

    GemmCore g;
    g.init(smem_u32(smraw), tid, A, W, bm, bn);
    g.run();

    #pragma unroll
    for (int mf = 0; mf < 4; mf++) {
        const int m0 = bm * 128 + wm * 64 + mf * 16 + (lane >> 2);
        #pragma unroll
        for (int nf = 0; nf < 4; nf++) {
            const int nc = bn * 128 + wn * 32 + nf * 8 + (lane & 3) * 2;
            const float b0 = __ldg(bias + nc), b1 = __ldg(bias + nc + 1);
            float2 lo, hi;
            lo.x = g.acc[mf][nf][0] + b0; lo.y = g.acc[mf][nf][1] + b1;
            hi.x = g.acc[mf][nf][2] + b0; hi.y = g.acc[mf][nf][3] + b1;
            *(float2*)(C + (size_t)m0 * 1024 + nc)       = lo;
            *(float2*)(C + (size_t)(m0 + 8) * 1024 + nc) = hi;
        }
    }
}

// ---------------------------------------------------------------------------
// All fp32->fp16 conversions in ONE launch. grid 20480:
//   [0,16384)      x  -> g_xs
//   [16384,17408)  Wq -> g_wqkv[0:1024)
//   [17408,18432)  Wk -> g_wqkv[1024:2048)
//   [18432,19456)  Wv -> g_wqkv[2048:3072)
//   [19456,20480)  Wo -> g_wos
// ---------------------------------------------------------------------------
__global__ __launch_bounds__(256) void conv_all(
    const float* __restrict__ x,  const float* __restrict__ Wq,
    const float* __restrict__ Wk, const float* __restrict__ Wv,
    const float* __restrict__ Wo)
{
    const int b = blockIdx.x;
    const float* src;
    __half* dst;
    if (b < MT) {
        src = x + (size_t)b * 1024;
        dst = g_xs + (size_t)b * 1024;
    } else if (b < MT + 1024) {
        src = Wq + (size_t)(b - MT) * 1024;
        dst = g_wqkv + (size_t)(b - MT) * 1024;
    } else if (b < MT + 2048) {
        src = Wk + (size_t)(b - MT - 1024) * 1024;
        dst = g_wqkv + (size_t)(b - MT) * 1024;
    } else if (b < MT + 3072) {
        src = Wv + (size_t)(b - MT - 2048) * 1024;
        dst = g_wqkv + (size_t)(b - MT) * 1024;
    } else {
        src = Wo + (size_t)(b - MT - 3072) * 1024;
        dst = g_wos + (size_t)(b - MT - 3072) * 1024;
    }
    const int c = threadIdx.x * 4;
    float4 v = *(const float4*)(src + c);
    __half2* d = (__half2*)(dst + c);
    d[0] = __half2(__float2half(v.x), __float2half(v.y));
    d[1] = __half2(__float2half(v.z), __float2half(v.w));
}

// ---------------------------------------------------------------------------
// KV summary (HMMA): per (b,h,split): kv[64,64] = k^T @ v over 512 t.
// grid (64, 8), 8 warps: 2 (m=dk) x 4 (n=dm). Plain stores to partials.
// ---------------------------------------------------------------------------
__global__ __launch_bounds__(256) void kv_hmma(
    const __half* __restrict__ k16, const __half* __restrict__ v16)
{
    __shared__ __align__(16) char sm[4 * 2 * 32 * RS64];
    const uint32_t smb = smem_u32(sm);
    const int tid = threadIdx.x, lane = tid & 31, wid = tid >> 5;
    const int wm = wid >> 2, wn = wid & 3;
    const int bh = blockIdx.x, b = bh >> 4, h = bh & 15;
    const int spl = blockIdx.y;
    const int t0 = spl * 512;
    static constexpr int NCH = 16;
    static constexpr int STG = 2 * 32 * RS64;

    const int lrow = tid >> 3, lseg = tid & 7;
    const __half* gk = k16 + (size_t)(b * TT + t0 + lrow) * 1024 + h * 64 + lseg * 8;
    const __half* gv = v16 + (size_t)(b * TT + t0 + lrow) * 1024 + h * 64 + lseg * 8;
    const uint32_t sdst = (uint32_t)lrow * RS64 + lseg * 16;

    auto load_chunk = [&](int ch) {
        const uint32_t st = smb + (ch & 3) * STG;
        const size_t go = (size_t)ch * 32 * 1024;
        CP_ASYNC16(st + sdst,             gk + go);
        CP_ASYNC16(st + 32 * RS64 + sdst, gv + go);
        CP_COMMIT();
    };

    const uint32_t trow = (lane & 7) + ((lane >> 4) & 1) * 8;
    const uint32_t tcol = ((lane >> 3) & 1) * 8;
    const uint32_t a_base = trow * RS64 + (wm * 32 + tcol) * 2;
    const uint32_t b_base = 32 * RS64 + trow * RS64 + (wn * 16 + tcol) * 2;

    float acc[2][2][4];
    #pragma unroll
    for (int i = 0; i < 2; i++)
        #pragma unroll
        for (int j = 0; j < 2; j++)
            #pragma unroll
            for (int r = 0; r < 4; r++) acc[i][j][r] = 0.0f;
    float ksacc = 0.0f;

    load_chunk(0); load_chunk(1); load_chunk(2);

    #pragma unroll 1
    for (int ch = 0; ch < NCH; ch++) {
        if (ch < NCH - 2)       cp_wait<2>();
        else if (ch == NCH - 2) cp_wait<1>();
        else                    cp_wait<0>();
        __syncthreads();
        if (ch + 3 < NCH) load_chunk(ch + 3);

        const uint32_t st = smb + (ch & 3) * STG;
        #pragma unroll
        for (int ks = 0; ks < 2; ks++) {
            const uint32_t ko = ks * 16 * RS64;
            uint32_t a[2][4], bfr[4];
            ldsm_x4_t(a[0], st + a_base + ko);
            ldsm_x4_t(a[1], st + a_base + ko + 16 * 2);
            ldsm_x4_t(bfr,  st + b_base + ko);
            #pragma unroll
            for (int mf = 0; mf < 2; mf++)
                #pragma unroll
                for (int nf = 0; nf < 2; nf++)
                    mma_fp16(acc[mf][nf], a[mf], bfr[nf], bfr[nf + 2]);
        }
        if (tid < 64) {
            const __half* kc = (const __half*)(sm + (ch & 3) * STG);
            #pragma unroll
            for (int r = 0; r < 32; r++)
                ksacc += __half2float(*(const __half*)
                    ((const char*)kc + r * RS64 + tid * 2));
        }
    }

    // plain stores: warps tile 64x64 disjointly
    float* kvb = g_kvp + ((size_t)bh * NSPL + spl) * (DKK * DKK);
    #pragma unroll
    for (int mf = 0; mf < 2; mf++) {
        const int row = wm * 32 + mf * 16 + (lane >> 2);
        #pragma unroll
        for (int nf = 0; nf < 2; nf++) {
            const int col = wn * 16 + nf * 8 + (lane & 3) * 2;
            *(float2*)&kvb[row * 64 + col] =
                make_float2(acc[mf][nf][0], acc[mf][nf][1]);
            *(float2*)&kvb[(row + 8) * 64 + col] =
                make_float2(acc[mf][nf][2], acc[mf][nf][3]);
        }
    }
    if (tid < 64) g_ksp[((size_t)bh * NSPL + spl) * 64 + tid] = ksacc;
}

// ---------------------------------------------------------------------------
// kv fixup: sum partials -> fp16 kv^T; kse = ksum + eps. grid 64.
// ---------------------------------------------------------------------------
__global__ __launch_bounds__(256) void kv_fix()
{
    const int bh = blockIdx.x;
    const float* base = g_kvp + (size_t)bh * NSPL * 4096;
    __half* kvT = g_kvT + (size_t)bh * 4096;
    for (int i = threadIdx.x; i < 4096; i += 256) {
        float s = 0.0f;
        #pragma unroll
        for (int p = 0; p < NSPL; p++) s += base[p * 4096 + i];
        const int dk = i >> 6, dm = i & 63;   // i = dk*64 + dm
        kvT[dm * 64 + dk] = __float2half(s);
    }
    if (threadIdx.x < 64) {
        float s = 0.0f;
        #pragma unroll
        for (int p = 0; p < NSPL; p++)
            s += g_ksp[((size_t)bh * NSPL + p) * 64 + threadIdx.x];
        g_kse[bh * 64 + threadIdx.x] = s + EPSV;
    }
}

// ---------------------------------------------------------------------------
// Attention apply (HMMA): out[t,dm] = z[t] * (q[t,:] @ kv[:,dm]), fp16 out.
// grid (64, 32), 8 warps: 4 (m=t) x 2 (n=dm).
// ---------------------------------------------------------------------------
__global__ __launch_bounds__(256) void attn_hmma(
    const __half* __restrict__ q16, __half* __restrict__ out)
{
    __shared__ __align__(16) char smq[128 * RS64];
    __shared__ __align__(16) char smkv[64 * RS64];
    __shared__ float zs[128];
    __shared__ float kse[64];

    const uint32_t sq = smem_u32(smq), skv = smem_u32(smkv);
    const int tid = threadIdx.x, lane = tid & 31, wid = tid >> 5;
    const int wm = wid >> 1, wn = wid & 1;
    const int bh = blockIdx.x, b = bh >> 4, h = bh & 15;
    const int t0 = blockIdx.y * 128;

    {
        const __half* gq = q16 + (size_t)(b * TT + t0) * 1024 + h * 64;
        #pragma unroll
        for (int i = 0; i < 4; i++) {
            const int s = i * 256 + tid;
            const int r = s >> 3, c = s & 7;
            CP_ASYNC16(sq + r * RS64 + c * 16, gq + (size_t)r * 1024 + c * 8);
        }
        const __half* gkv = g_kvT + (size_t)bh * 4096;
        #pragma unroll
        for (int i = 0; i < 2; i++) {
            const int s = i * 256 + tid;
            const int r = s >> 3, c = s & 7;
            CP_ASYNC16(skv + r * RS64 + c * 16, gkv + r * 64 + c * 8);
        }
        CP_COMMIT();
    }
    if (tid < 64) kse[tid] = g_kse[bh * 64 + tid];
    cp_wait<0>();
    __syncthreads();

    if (tid < 128) {
        float s = EPSV;
        const char* qrow = smq + tid * RS64;
        #pragma unroll
        for (int d = 0; d < 64; d++)
            s = fmaf(__half2float(*(const __half*)(qrow + d * 2)), kse[d], s);
        zs[tid] = 1.0f / s;
    }
    __syncthreads();

    const uint32_t a_base = (uint32_t)(wm * 32 + (lane & 15)) * RS64 + (lane >> 4) * 16;
    const uint32_t b_base = (uint32_t)(wn * 32 + (lane & 15)) * RS64 + (lane >> 4) * 16;

    float acc[2][4][4];
    #pragma unroll
    for (int i = 0; i < 2; i++)
        #pragma unroll
        for (int j = 0; j < 4; j++)
            #pragma unroll
            for (int r = 0; r < 4; r++) acc[i][j][r] = 0.0f;

    #pragma unroll
    for (int ks = 0; ks < 4; ks++) {
        const uint32_t ko = ks * 32;
        uint32_t a[2][4], bl[2][4];
        ldsm_x4(a[0], sq + a_base + ko);
        ldsm_x4(a[1], sq + a_base + 16 * RS64 + ko);
        ldsm_x4(bl[0], skv + b_base + ko);
        ldsm_x4(bl[1], skv + b_base + 16 * RS64 + ko);
        #pragma unroll
        for (int mf = 0; mf < 2; mf++)
            #pragma unroll
            for (int nf = 0; nf < 4; nf++)
                mma_fp16(acc[mf][nf], a[mf],
                         bl[nf >> 1][nf & 1], bl[nf >> 1][(nf & 1) + 2]);
    }

    #pragma unroll
    for (int mf = 0; mf < 2; mf++) {
        const int row = wm * 32 + mf * 16 + (lane >> 2);
        const float z0 = zs[row], z1 = zs[row + 8];
        #pragma unroll
        for (int nf = 0; nf < 4; nf++) {
            const int col = wn * 32 + nf * 8 + (lane & 3) * 2;
            __half2* o0 = (__half2*)(out + (size_t)(b * TT + t0 + row) * 1024 + h * 64 + col);
            __half2* o1 = (__half2*)(out + (size_t)(b * TT + t0 + row + 8) * 1024 + h * 64 + col);
            *o0 = __half2(__float2half(acc[mf][nf][0] * z0),
                          __float2half(acc[mf][nf][1] * z0));
            *o1 = __half2(__float2half(acc[mf][nf][2] * z1),
                          __float2half(acc[mf][nf][3] * z1));
        }
    }
}

// ---------------------------------------------------------------------------
extern "C" void kernel_launch(void* const* d_in, const int* in_sizes, int n_in,
                              void* d_out, int out_size)
{
    const float* x  = (const float*)d_in[0];
    const float* Wq = (const float*)d_in[1];
    const float* bq = (const float*)d_in[2];
    const float* Wk = (const float*)d_in[3];
    const float* bk = (const float*)d_in[4];
    const float* Wv = (const float*)d_in[5];
    const float* bv = (const float*)d_in[6];
    const float* Wo = (const float*)d_in[7];
    const float* bo = (const float*)d_in[8];
    float* out = (float*)d_out;

    __half *xs, *as, *wqkv, *wos, *qp, *kp, *vp;
    cudaGetSymbolAddress((void**)&xs,   g_xs);
    cudaGetSymbolAddress((void**)&as,   g_as);
    cudaGetSymbolAddress((void**)&wqkv, g_wqkv);
    cudaGetSymbolAddress((void**)&wos,  g_wos);
    cudaGetSymbolAddress((void**)&qp,   g_q16);
    cudaGetSymbolAddress((void**)&kp,   g_k16);
    cudaGetSymbolAddress((void**)&vp,   g_v16);

    cudaFuncSetAttribute(gemm_qkv, cudaFuncAttributeMaxDynamicSharedMemorySize, SMEM_GEMM);
    cudaFuncSetAttribute(gemm_out, cudaFuncAttributeMaxDynamicSharedMemorySize, SMEM_GEMM);

    conv_all<<<MT + 4 * 1024, 256>>>(x, Wq, Wk, Wv, Wo);

    gemm_qkv<<<dim3(24, MT / 128), 256, SMEM_GEMM>>>(
        xs, wqkv, bq, bk, bv, qp, kp, vp);

    kv_hmma<<<dim3(BB * HH, NSPL), 256>>>(kp, vp);
    kv_fix<<<BB * HH, 256>>>();
    attn_hmma<<<dim3(BB * HH, TT / 128), 256>>>(qp, as);

    gemm_out<<<dim3(DD / 128, MT / 128), 256, SMEM_GEMM>>>(as, wos, bo, out);
}

// round 11
// speedup vs baseline: 1.0692x; 1.0145x over previous
#include <cuda_runtime.h>
#include <cuda_fp16.h>
#include <math.h>
#include <stdint.h>

// Problem constants
static constexpr int BB  = 4;
static constexpr int TT  = 4096;
static constexpr int DD  = 1024;
static constexpr int HH  = 16;
static constexpr int DKK = 64;
static constexpr int MT  = BB * TT;      // 16384 tokens
static constexpr int KK  = DD;           // fp16 GEMM K = 1024
static constexpr int BKC = 32;           // K-chunk (fp16 elems)
static constexpr int NCHUNK = KK / BKC;  // 32
static constexpr int NSPL = 8;           // kv t-splits
#define EPSV 1e-6f

// GEMM SMEM geometry: rows padded to 40 fp16 (80 B) for conflict-free ldmatrix
static constexpr int ROWB  = 80;
static constexpr int TILEB = 128 * ROWB;
static constexpr int STGB  = 2 * TILEB;
static constexpr int NSTG  = 4;
static constexpr int SMEM_GEMM = NSTG * STGB; // 81920 B

// kv/attn smem row stride for 64-wide fp16 tiles: 128B data + 16B pad
static constexpr int RS64 = 144;

// ---------------------------------------------------------------------------
// Scratch (device globals — no allocation allowed)
// ---------------------------------------------------------------------------
__device__ __half g_xs[(size_t)MT * KK];      // x fp16
__device__ __half g_as[(size_t)MT * KK];      // attn out fp16
__device__ __half g_wqkv[3 * DD * KK];        // packed Wq|Wk|Wv fp16
__device__ __half g_wos[DD * KK];             // Wo fp16
__device__ __half g_q16[(size_t)MT * DD];
__device__ __half g_k16[(size_t)MT * DD];
__device__ __half g_v16[(size_t)MT * DD];
__device__ float  g_kvp[BB * HH * NSPL * DKK * DKK];  // kv partials (8 MB)
__device__ float  g_ksp[BB * HH * NSPL * DKK];        // ksum partials
__device__ __half g_kvT[BB * HH * DKK * DKK];         // fp16 kv^T
__device__ float  g_kse[BB * HH * DKK];               // ksum + eps

__device__ __forceinline__ float phi_act(float x) {
    return x > 0.0f ? x + 1.0f : expf(x);
}

// ---------------------------------------------------------------------------
// PTX helpers (baseline sm_80+ features only)
// ---------------------------------------------------------------------------
__device__ __forceinline__ uint32_t smem_u32(const void* p) {
    uint32_t a;
    asm("{ .reg .u64 t; cvta.to.shared.u64 t, %1; cvt.u32.u64 %0, t; }"
        : "=r"(a) : "l"(p));
    return a;
}

#define CP_ASYNC16(sm, gp) \
    asm volatile("cp.async.cg.shared.global [%0], [%1], 16;" :: "r"(sm), "l"(gp))
#define CP_COMMIT() asm volatile("cp.async.commit_group;")
template <int N> __device__ __forceinline__ void cp_wait() {
    asm volatile("cp.async.wait_group %0;" :: "n"(N));
}

__device__ __forceinline__ void ldsm_x4(uint32_t* r, uint32_t addr) {
    asm volatile("ldmatrix.sync.aligned.m8n8.x4.shared.b16 {%0,%1,%2,%3}, [%4];"
                 : "=r"(r[0]), "=r"(r[1]), "=r"(r[2]), "=r"(r[3]) : "r"(addr));
}
__device__ __forceinline__ void ldsm_x4_t(uint32_t* r, uint32_t addr) {
    asm volatile("ldmatrix.sync.aligned.m8n8.x4.trans.shared.b16 {%0,%1,%2,%3}, [%4];"
                 : "=r"(r[0]), "=r"(r[1]), "=r"(r[2]), "=r"(r[3]) : "r"(addr));
}

__device__ __forceinline__ void mma_fp16(float* c, const uint32_t* a,
                                         uint32_t b0, uint32_t b1) {
    asm volatile(
        "mma.sync.aligned.m16n8k16.row.col.f32.f16.f16.f32 "
        "{%0,%1,%2,%3}, {%4,%5,%6,%7}, {%8,%9}, {%0,%1,%2,%3};"
        : "+f"(c[0]), "+f"(c[1]), "+f"(c[2]), "+f"(c[3])
        : "r"(a[0]), "r"(a[1]), "r"(a[2]), "r"(a[3]), "r"(b0), "r"(b1));
}

// ---------------------------------------------------------------------------
// GEMM mainloop core (at the HMMA issue floor)
// ---------------------------------------------------------------------------
struct GemmCore {
    uint32_t tiles, sw0, a_off, b_off;
    const char *Ag, *Wg;
    float acc[4][4][4];

    __device__ __forceinline__ void init(uint32_t tiles_, int tid,
                                         const __half* A, const __half* W,
                                         int bm, int bn) {
        tiles = tiles_;
        const int wid  = tid >> 5, lane = tid & 31;
        const int wm   = wid >> 2, wn = wid & 3;
        const int lrow = tid >> 1;
        const int lc16 = (tid & 1) * 2;
        sw0 = (uint32_t)lrow * ROWB + lc16 * 16;
        Ag = (const char*)(A + (size_t)(bm * 128 + lrow) * KK) + lc16 * 16;
        Wg = (const char*)(W + (size_t)(bn * 128 + lrow) * KK) + lc16 * 16;
        a_off = (uint32_t)(wm * 64 + (lane & 15)) * ROWB + (lane >> 4) * 16;
        b_off = TILEB + (uint32_t)(wn * 32 + (lane & 15)) * ROWB + (lane >> 4) * 16;
        #pragma unroll
        for (int i = 0; i < 4; i++)
            #pragma unroll
            for (int j = 0; j < 4; j++)
                #pragma unroll
                for (int r = 0; r < 4; r++) acc[i][j][r] = 0.0f;
    }

    __device__ __forceinline__ void load_chunk(int kc) {
        const uint32_t st = tiles + (kc & (NSTG - 1)) * STGB;
        const char* ga = Ag + (size_t)kc * (BKC * 2);
        const char* gb = Wg + (size_t)kc * (BKC * 2);
        CP_ASYNC16(st + sw0,              ga);
        CP_ASYNC16(st + sw0 + 16,         ga + 16);
        CP_ASYNC16(st + TILEB + sw0,      gb);
        CP_ASYNC16(st + TILEB + sw0 + 16, gb + 16);
        CP_COMMIT();
    }

    __device__ __forceinline__ void run() {
        load_chunk(0); load_chunk(1); load_chunk(2);
        #pragma unroll 1
        for (int kc = 0; kc < NCHUNK; kc++) {
            if (kc < NCHUNK - 2)       cp_wait<2>();
            else if (kc == NCHUNK - 2) cp_wait<1>();
            else                       cp_wait<0>();
            __syncthreads();
            if (kc + 3 < NCHUNK) load_chunk(kc + 3);

            const uint32_t st = tiles + (kc & (NSTG - 1)) * STGB;
            #pragma unroll
            for (int ks = 0; ks < 2; ks++) {
                const uint32_t kb = ks * 32;
                uint32_t a[4][4], b[2][4];
                #pragma unroll
                for (int mf = 0; mf < 4; mf++)
                    ldsm_x4(a[mf], st + a_off + mf * (16 * ROWB) + kb);
                #pragma unroll
                for (int nf2 = 0; nf2 < 2; nf2++)
                    ldsm_x4(b[nf2], st + b_off + nf2 * (16 * ROWB) + kb);
                #pragma unroll
                for (int mf = 0; mf < 4; mf++) {
                    #pragma unroll
                    for (int nf = 0; nf < 4; nf++)
                        mma_fp16(acc[mf][nf], a[mf],
                                 b[nf >> 1][nf & 1], b[nf >> 1][(nf & 1) + 2]);
                }
            }
        }
    }
};

// ---------------------------------------------------------------------------
// Fused QKV GEMM -> fp16 outputs (seg 0=Q+phi, 1=K+phi, 2=V); grid (24, 128)
// ---------------------------------------------------------------------------
__global__ void __launch_bounds__(256, 2) gemm_qkv(
    const __half* __restrict__ A, const __half* __restrict__ Wqkv,
    const float* __restrict__ bq, const float* __restrict__ bk,
    const float* __restrict__ bv,
    __half* __restrict__ Cq, __half* __restrict__ Ck, __half* __restrict__ Cv)
{
    extern __shared__ char smraw[];
    const int tid = threadIdx.x;
    const int wid = tid >> 5, lane = tid & 31;
    const int wm  = wid >> 2, wn = wid & 3;
    const int bm  = blockIdx.y, bn = blockIdx.x;

    const int seg = bn >> 3;
    const float* bias = seg == 0 ? bq : (seg == 1 ? bk : bv);
    __half* C = seg == 0 ? Cq : (seg == 1 ? Ck : Cv);
    const bool act = seg < 2;

    GemmCore g;
    g.init(smem_u32(smraw), tid, A, Wqkv, bm, bn);
    g.run();

    #pragma unroll
    for (int mf = 0; mf < 4; mf++) {
        const int m0 = bm * 128 + wm * 64 + mf * 16 + (lane >> 2);
        #pragma unroll
        for (int nf = 0; nf < 4; nf++) {
            const int nc = (bn & 7) * 128 + wn * 32 + nf * 8 + (lane & 3) * 2;
            const float b0 = __ldg(bias + nc), b1 = __ldg(bias + nc + 1);
            float l0 = g.acc[mf][nf][0] + b0, l1 = g.acc[mf][nf][1] + b1;
            float h0 = g.acc[mf][nf][2] + b0, h1 = g.acc[mf][nf][3] + b1;
            if (act) { l0 = phi_act(l0); l1 = phi_act(l1);
                       h0 = phi_act(h0); h1 = phi_act(h1); }
            *(__half2*)(C + (size_t)m0 * 1024 + nc) =
                __half2(__float2half(l0), __float2half(l1));
            *(__half2*)(C + (size_t)(m0 + 8) * 1024 + nc) =
                __half2(__float2half(h0), __float2half(h1));
        }
    }
}

// ---------------------------------------------------------------------------
// Output GEMM: out = attn_fp16 @ Wo^T + bo  -> fp32
// ---------------------------------------------------------------------------
__global__ void __launch_bounds__(256, 2) gemm_out(
    const __half* __restrict__ A, const __half* __restrict__ W,
    const float* __restrict__ bias, float* __restrict__ C)
{
    extern __shared__ char smraw[];
    const int tid = threadIdx.x;
    const int wid = tid >> 5, lane = tid & 31;
    const int wm  = wid >> 2, wn = wid & 3;
    const int bm  = blockIdx.y, bn = blockIdx.x;

    GemmCore g;
    g.init(smem_u32(smraw), tid, A, W, bm, bn);
    g.run();

    #pragma unroll
    for (int mf = 0; mf < 4; mf++) {
        const int m0 = bm * 128 + wm * 64 + mf * 16 + (lane >> 2);
        #pragma unroll
        for (int nf = 0; nf < 4; nf++) {
            const int nc = bn * 128 + wn * 32 + nf * 8 + (lane & 3) * 2;
            const float b0 = __ldg(bias + nc), b1 = __ldg(bias + nc + 1);
            float2 lo, hi;
            lo.x = g.acc[mf][nf][0] + b0; lo.y = g.acc[mf][nf][1] + b1;
            hi.x = g.acc[mf][nf][2] + b0; hi.y = g.acc[mf][nf][3] + b1;
            *(float2*)(C + (size_t)m0 * 1024 + nc)       = lo;
            *(float2*)(C + (size_t)(m0 + 8) * 1024 + nc) = hi;
        }
    }
}

// ---------------------------------------------------------------------------
// All fp32->fp16 conversions in ONE launch, 4 rows/block for MLP=4.
// grid 5120: rows [0,16384)=x, [16384,17408)=Wq, [17408,18432)=Wk,
//            [18432,19456)=Wv, [19456,20480)=Wo. All boundaries %4==0.
// ---------------------------------------------------------------------------
__global__ __launch_bounds__(256) void conv_all(
    const float* __restrict__ x,  const float* __restrict__ Wq,
    const float* __restrict__ Wk, const float* __restrict__ Wv,
    const float* __restrict__ Wo)
{
    const int r0 = blockIdx.x * 4;   // first row of this block
    const float* src;
    __half* dst;
    if (r0 < MT) {
        src = x + (size_t)r0 * 1024;
        dst = g_xs + (size_t)r0 * 1024;
    } else if (r0 < MT + 1024) {
        src = Wq + (size_t)(r0 - MT) * 1024;
        dst = g_wqkv + (size_t)(r0 - MT) * 1024;
    } else if (r0 < MT + 2048) {
        src = Wk + (size_t)(r0 - MT - 1024) * 1024;
        dst = g_wqkv + (size_t)(r0 - MT) * 1024;
    } else if (r0 < MT + 3072) {
        src = Wv + (size_t)(r0 - MT - 2048) * 1024;
        dst = g_wqkv + (size_t)(r0 - MT) * 1024;
    } else {
        src = Wo + (size_t)(r0 - MT - 3072) * 1024;
        dst = g_wos + (size_t)(r0 - MT - 3072) * 1024;
    }
    // 4 rows = 4096 floats = 1024 float4; 4 independent loads per thread
    const int t = threadIdx.x;
    float4 v0 = *(const float4*)(src + (t           ) * 4);
    float4 v1 = *(const float4*)(src + (t + 256     ) * 4);
    float4 v2 = *(const float4*)(src + (t + 512     ) * 4);
    float4 v3 = *(const float4*)(src + (t + 768     ) * 4);
    __half2* d;
    d = (__half2*)(dst + (size_t)t * 4);
    d[0] = __half2(__float2half(v0.x), __float2half(v0.y));
    d[1] = __half2(__float2half(v0.z), __float2half(v0.w));
    d = (__half2*)(dst + (size_t)(t + 256) * 4);
    d[0] = __half2(__float2half(v1.x), __float2half(v1.y));
    d[1] = __half2(__float2half(v1.z), __float2half(v1.w));
    d = (__half2*)(dst + (size_t)(t + 512) * 4);
    d[0] = __half2(__float2half(v2.x), __float2half(v2.y));
    d[1] = __half2(__float2half(v2.z), __float2half(v2.w));
    d = (__half2*)(dst + (size_t)(t + 768) * 4);
    d[0] = __half2(__float2half(v3.x), __float2half(v3.y));
    d[1] = __half2(__float2half(v3.z), __float2half(v3.w));
}

// ---------------------------------------------------------------------------
// KV summary (HMMA): per (b,h,split): kv[64,64] = k^T @ v over 512 t.
// grid (64, 8), 8 warps: 2 (m=dk) x 4 (n=dm). Plain stores to partials.
// ---------------------------------------------------------------------------
__global__ __launch_bounds__(256) void kv_hmma(
    const __half* __restrict__ k16, const __half* __restrict__ v16)
{
    __shared__ __align__(16) char sm[4 * 2 * 32 * RS64];
    const uint32_t smb = smem_u32(sm);
    const int tid = threadIdx.x, lane = tid & 31, wid = tid >> 5;
    const int wm = wid >> 2, wn = wid & 3;
    const int bh = blockIdx.x, b = bh >> 4, h = bh & 15;
    const int spl = blockIdx.y;
    const int t0 = spl * 512;
    static constexpr int NCH = 16;
    static constexpr int STG = 2 * 32 * RS64;

    const int lrow = tid >> 3, lseg = tid & 7;
    const __half* gk = k16 + (size_t)(b * TT + t0 + lrow) * 1024 + h * 64 + lseg * 8;
    const __half* gv = v16 + (size_t)(b * TT + t0 + lrow) * 1024 + h * 64 + lseg * 8;
    const uint32_t sdst = (uint32_t)lrow * RS64 + lseg * 16;

    auto load_chunk = [&](int ch) {
        const uint32_t st = smb + (ch & 3) * STG;
        const size_t go = (size_t)ch * 32 * 1024;
        CP_ASYNC16(st + sdst,             gk + go);
        CP_ASYNC16(st + 32 * RS64 + sdst, gv + go);
        CP_COMMIT();
    };

    const uint32_t trow = (lane & 7) + ((lane >> 4) & 1) * 8;
    const uint32_t tcol = ((lane >> 3) & 1) * 8;
    const uint32_t a_base = trow * RS64 + (wm * 32 + tcol) * 2;
    const uint32_t b_base = 32 * RS64 + trow * RS64 + (wn * 16 + tcol) * 2;

    float acc[2][2][4];
    #pragma unroll
    for (int i = 0; i < 2; i++)
        #pragma unroll
        for (int j = 0; j < 2; j++)
            #pragma unroll
            for (int r = 0; r < 4; r++) acc[i][j][r] = 0.0f;
    float ksacc = 0.0f;

    load_chunk(0); load_chunk(1); load_chunk(2);

    #pragma unroll 1
    for (int ch = 0; ch < NCH; ch++) {
        if (ch < NCH - 2)       cp_wait<2>();
        else if (ch == NCH - 2) cp_wait<1>();
        else                    cp_wait<0>();
        __syncthreads();
        if (ch + 3 < NCH) load_chunk(ch + 3);

        const uint32_t st = smb + (ch & 3) * STG;
        #pragma unroll
        for (int ks = 0; ks < 2; ks++) {
            const uint32_t ko = ks * 16 * RS64;
            uint32_t a[2][4], bfr[4];
            ldsm_x4_t(a[0], st + a_base + ko);
            ldsm_x4_t(a[1], st + a_base + ko + 16 * 2);
            ldsm_x4_t(bfr,  st + b_base + ko);
            #pragma unroll
            for (int mf = 0; mf < 2; mf++)
                #pragma unroll
                for (int nf = 0; nf < 2; nf++)
                    mma_fp16(acc[mf][nf], a[mf], bfr[nf], bfr[nf + 2]);
        }
        if (tid < 64) {
            const __half* kc = (const __half*)(sm + (ch & 3) * STG);
            #pragma unroll
            for (int r = 0; r < 32; r++)
                ksacc += __half2float(*(const __half*)
                    ((const char*)kc + r * RS64 + tid * 2));
        }
    }

    float* kvb = g_kvp + ((size_t)bh * NSPL + spl) * (DKK * DKK);
    #pragma unroll
    for (int mf = 0; mf < 2; mf++) {
        const int row = wm * 32 + mf * 16 + (lane >> 2);
        #pragma unroll
        for (int nf = 0; nf < 2; nf++) {
            const int col = wn * 16 + nf * 8 + (lane & 3) * 2;
            *(float2*)&kvb[row * 64 + col] =
                make_float2(acc[mf][nf][0], acc[mf][nf][1]);
            *(float2*)&kvb[(row + 8) * 64 + col] =
                make_float2(acc[mf][nf][2], acc[mf][nf][3]);
        }
    }
    if (tid < 64) g_ksp[((size_t)bh * NSPL + spl) * 64 + tid] = ksacc;
}

// ---------------------------------------------------------------------------
// kv fixup (parallel): grid 512 = 64 bh x 8 parts. Each block reduces 512
// kv elements across the 8 partials; part-0 blocks also reduce ksum.
// ---------------------------------------------------------------------------
__global__ __launch_bounds__(256) void kv_fix()
{
    const int bh   = blockIdx.x >> 3;
    const int part = blockIdx.x & 7;
    const float* base = g_kvp + (size_t)bh * NSPL * 4096;
    __half* kvT = g_kvT + (size_t)bh * 4096;

    #pragma unroll
    for (int u = 0; u < 2; u++) {
        const int i = part * 512 + u * 256 + threadIdx.x;  // i = dk*64 + dm
        float s = 0.0f;
        #pragma unroll
        for (int p = 0; p < NSPL; p++) s += base[p * 4096 + i];
        const int dk = i >> 6, dm = i & 63;
        kvT[dm * 64 + dk] = __float2half(s);
    }
    if (part == 0 && threadIdx.x < 64) {
        float s = 0.0f;
        #pragma unroll
        for (int p = 0; p < NSPL; p++)
            s += g_ksp[((size_t)bh * NSPL + p) * 64 + threadIdx.x];
        g_kse[bh * 64 + threadIdx.x] = s + EPSV;
    }
}

// ---------------------------------------------------------------------------
// Attention apply (HMMA): out[t,dm] = z[t] * (q[t,:] @ kv[:,dm]), fp16 out.
// grid (64, 32), 8 warps: 4 (m=t) x 2 (n=dm).
// ---------------------------------------------------------------------------
__global__ __launch_bounds__(256) void attn_hmma(
    const __half* __restrict__ q16, __half* __restrict__ out)
{
    __shared__ __align__(16) char smq[128 * RS64];
    __shared__ __align__(16) char smkv[64 * RS64];
    __shared__ float zs[128];
    __shared__ float kse[64];

    const uint32_t sq = smem_u32(smq), skv = smem_u32(smkv);
    const int tid = threadIdx.x, lane = tid & 31, wid = tid >> 5;
    const int wm = wid >> 1, wn = wid & 1;
    const int bh = blockIdx.x, b = bh >> 4, h = bh & 15;
    const int t0 = blockIdx.y * 128;

    {
        const __half* gq = q16 + (size_t)(b * TT + t0) * 1024 + h * 64;
        #pragma unroll
        for (int i = 0; i < 4; i++) {
            const int s = i * 256 + tid;
            const int r = s >> 3, c = s & 7;
            CP_ASYNC16(sq + r * RS64 + c * 16, gq + (size_t)r * 1024 + c * 8);
        }
        const __half* gkv = g_kvT + (size_t)bh * 4096;
        #pragma unroll
        for (int i = 0; i < 2; i++) {
            const int s = i * 256 + tid;
            const int r = s >> 3, c = s & 7;
            CP_ASYNC16(skv + r * RS64 + c * 16, gkv + r * 64 + c * 8);
        }
        CP_COMMIT();
    }
    if (tid < 64) kse[tid] = g_kse[bh * 64 + tid];
    cp_wait<0>();
    __syncthreads();

    if (tid < 128) {
        float s = EPSV;
        const char* qrow = smq + tid * RS64;
        #pragma unroll
        for (int d = 0; d < 64; d++)
            s = fmaf(__half2float(*(const __half*)(qrow + d * 2)), kse[d], s);
        zs[tid] = 1.0f / s;
    }
    __syncthreads();

    const uint32_t a_base = (uint32_t)(wm * 32 + (lane & 15)) * RS64 + (lane >> 4) * 16;
    const uint32_t b_base = (uint32_t)(wn * 32 + (lane & 15)) * RS64 + (lane >> 4) * 16;

    float acc[2][4][4];
    #pragma unroll
    for (int i = 0; i < 2; i++)
        #pragma unroll
        for (int j = 0; j < 4; j++)
            #pragma unroll
            for (int r = 0; r < 4; r++) acc[i][j][r] = 0.0f;

    #pragma unroll
    for (int ks = 0; ks < 4; ks++) {
        const uint32_t ko = ks * 32;
        uint32_t a[2][4], bl[2][4];
        ldsm_x4(a[0], sq + a_base + ko);
        ldsm_x4(a[1], sq + a_base + 16 * RS64 + ko);
        ldsm_x4(bl[0], skv + b_base + ko);
        ldsm_x4(bl[1], skv + b_base + 16 * RS64 + ko);
        #pragma unroll
        for (int mf = 0; mf < 2; mf++)
            #pragma unroll
            for (int nf = 0; nf < 4; nf++)
                mma_fp16(acc[mf][nf], a[mf],
                         bl[nf >> 1][nf & 1], bl[nf >> 1][(nf & 1) + 2]);
    }

    #pragma unroll
    for (int mf = 0; mf < 2; mf++) {
        const int row = wm * 32 + mf * 16 + (lane >> 2);
        const float z0 = zs[row], z1 = zs[row + 8];
        #pragma unroll
        for (int nf = 0; nf < 4; nf++) {
            const int col = wn * 32 + nf * 8 + (lane & 3) * 2;
            __half2* o0 = (__half2*)(out + (size_t)(b * TT + t0 + row) * 1024 + h * 64 + col);
            __half2* o1 = (__half2*)(out + (size_t)(b * TT + t0 + row + 8) * 1024 + h * 64 + col);
            *o0 = __half2(__float2half(acc[mf][nf][0] * z0),
                          __float2half(acc[mf][nf][1] * z0));
            *o1 = __half2(__float2half(acc[mf][nf][2] * z1),
                          __float2half(acc[mf][nf][3] * z1));
        }
    }
}

// ---------------------------------------------------------------------------
extern "C" void kernel_launch(void* const* d_in, const int* in_sizes, int n_in,
                              void* d_out, int out_size)
{
    const float* x  = (const float*)d_in[0];
    const float* Wq = (const float*)d_in[1];
    const float* bq = (const float*)d_in[2];
    const float* Wk = (const float*)d_in[3];
    const float* bk = (const float*)d_in[4];
    const float* Wv = (const float*)d_in[5];
    const float* bv = (const float*)d_in[6];
    const float* Wo = (const float*)d_in[7];
    const float* bo = (const float*)d_in[8];
    float* out = (float*)d_out;

    __half *xs, *as, *wqkv, *wos, *qp, *kp, *vp;
    cudaGetSymbolAddress((void**)&xs,   g_xs);
    cudaGetSymbolAddress((void**)&as,   g_as);
    cudaGetSymbolAddress((void**)&wqkv, g_wqkv);
    cudaGetSymbolAddress((void**)&wos,  g_wos);
    cudaGetSymbolAddress((void**)&qp,   g_q16);
    cudaGetSymbolAddress((void**)&kp,   g_k16);
    cudaGetSymbolAddress((void**)&vp,   g_v16);

    cudaFuncSetAttribute(gemm_qkv, cudaFuncAttributeMaxDynamicSharedMemorySize, SMEM_GEMM);
    cudaFuncSetAttribute(gemm_out, cudaFuncAttributeMaxDynamicSharedMemorySize, SMEM_GEMM);

    conv_all<<<(MT + 4 * 1024) / 4, 256>>>(x, Wq, Wk, Wv, Wo);

    gemm_qkv<<<dim3(24, MT / 128), 256, SMEM_GEMM>>>(
        xs, wqkv, bq, bk, bv, qp, kp, vp);

    kv_hmma<<<dim3(BB * HH, NSPL), 256>>>(kp, vp);
    kv_fix<<<BB * HH * 8, 256>>>();
    attn_hmma<<<dim3(BB * HH, TT / 128), 256>>>(qp, as);

    gemm_out<<<dim3(DD / 128, MT / 128), 256, SMEM_GEMM>>>(as, wos, bo, out);
}

// round 12
// speedup vs baseline: 1.0862x; 1.0159x over previous
#include <cuda_runtime.h>
#include <cuda_fp16.h>
#include <math.h>
#include <stdint.h>

// Problem constants
static constexpr int BB  = 4;
static constexpr int TT  = 4096;
static constexpr int DD  = 1024;
static constexpr int HH  = 16;
static constexpr int DKK = 64;
static constexpr int MT  = BB * TT;      // 16384 tokens
static constexpr int KK  = DD;           // fp16 GEMM K = 1024
static constexpr int BKC = 32;           // K-chunk (fp16 elems)
static constexpr int NCHUNK = KK / BKC;  // 32
static constexpr int NSPL = 8;           // kv t-splits
#define EPSV 1e-6f

// GEMM SMEM geometry: rows padded to 40 fp16 (80 B) for conflict-free ldmatrix
static constexpr int ROWB  = 80;
static constexpr int TILEB = 128 * ROWB;      // A tile bytes (128 rows)
static constexpr int STGB  = 2 * TILEB;
static constexpr int NSTG  = 4;
static constexpr int SMEM_GEMM = NSTG * STGB; // 81920 B

// gemm_out 128x64 variant
static constexpr int TILEB_B64 = 64 * ROWB;            // 5120
static constexpr int STGB64    = TILEB + TILEB_B64;    // 15360
static constexpr int SMEM_GEMM64 = NSTG * STGB64;      // 61440

// kv/attn smem row stride for 64-wide fp16 tiles: 128B data + 16B pad
static constexpr int RS64 = 144;

// ---------------------------------------------------------------------------
// Scratch (device globals — no allocation allowed)
// ---------------------------------------------------------------------------
__device__ __half g_xs[(size_t)MT * KK];      // x fp16
__device__ __half g_as[(size_t)MT * KK];      // attn out fp16
__device__ __half g_wqkv[3 * DD * KK];        // packed Wq|Wk|Wv fp16
__device__ __half g_wos[DD * KK];             // Wo fp16
__device__ __half g_q16[(size_t)MT * DD];
__device__ __half g_k16[(size_t)MT * DD];
__device__ __half g_v16[(size_t)MT * DD];
__device__ float  g_kvp[BB * HH * NSPL * DKK * DKK];  // kv partials (8 MB)
__device__ float  g_ksp[BB * HH * NSPL * DKK];        // ksum partials
__device__ __half g_kvT[BB * HH * DKK * DKK];         // fp16 kv^T
__device__ float  g_kse[BB * HH * DKK];               // ksum + eps

__device__ __forceinline__ float phi_act(float x) {
    return x > 0.0f ? x + 1.0f : expf(x);
}

// ---------------------------------------------------------------------------
// PTX helpers (baseline sm_80+ features only)
// ---------------------------------------------------------------------------
__device__ __forceinline__ uint32_t smem_u32(const void* p) {
    uint32_t a;
    asm("{ .reg .u64 t; cvta.to.shared.u64 t, %1; cvt.u32.u64 %0, t; }"
        : "=r"(a) : "l"(p));
    return a;
}

#define CP_ASYNC16(sm, gp) \
    asm volatile("cp.async.cg.shared.global [%0], [%1], 16;" :: "r"(sm), "l"(gp))
#define CP_COMMIT() asm volatile("cp.async.commit_group;")
template <int N> __device__ __forceinline__ void cp_wait() {
    asm volatile("cp.async.wait_group %0;" :: "n"(N));
}

__device__ __forceinline__ void ldsm_x4(uint32_t* r, uint32_t addr) {
    asm volatile("ldmatrix.sync.aligned.m8n8.x4.shared.b16 {%0,%1,%2,%3}, [%4];"
                 : "=r"(r[0]), "=r"(r[1]), "=r"(r[2]), "=r"(r[3]) : "r"(addr));
}
__device__ __forceinline__ void ldsm_x4_t(uint32_t* r, uint32_t addr) {
    asm volatile("ldmatrix.sync.aligned.m8n8.x4.trans.shared.b16 {%0,%1,%2,%3}, [%4];"
                 : "=r"(r[0]), "=r"(r[1]), "=r"(r[2]), "=r"(r[3]) : "r"(addr));
}

__device__ __forceinline__ void mma_fp16(float* c, const uint32_t* a,
                                         uint32_t b0, uint32_t b1) {
    asm volatile(
        "mma.sync.aligned.m16n8k16.row.col.f32.f16.f16.f32 "
        "{%0,%1,%2,%3}, {%4,%5,%6,%7}, {%8,%9}, {%0,%1,%2,%3};"
        : "+f"(c[0]), "+f"(c[1]), "+f"(c[2]), "+f"(c[3])
        : "r"(a[0]), "r"(a[1]), "r"(a[2]), "r"(a[3]), "r"(b0), "r"(b1));
}

// ---------------------------------------------------------------------------
// GEMM mainloop core, 128x128 tile (used by gemm_qkv)
// ---------------------------------------------------------------------------
struct GemmCore {
    uint32_t tiles, sw0, a_off, b_off;
    const char *Ag, *Wg;
    float acc[4][4][4];

    __device__ __forceinline__ void init(uint32_t tiles_, int tid,
                                         const __half* A, const __half* W,
                                         int bm, int bn) {
        tiles = tiles_;
        const int wid  = tid >> 5, lane = tid & 31;
        const int wm   = wid >> 2, wn = wid & 3;
        const int lrow = tid >> 1;
        const int lc16 = (tid & 1) * 2;
        sw0 = (uint32_t)lrow * ROWB + lc16 * 16;
        Ag = (const char*)(A + (size_t)(bm * 128 + lrow) * KK) + lc16 * 16;
        Wg = (const char*)(W + (size_t)(bn * 128 + lrow) * KK) + lc16 * 16;
        a_off = (uint32_t)(wm * 64 + (lane & 15)) * ROWB + (lane >> 4) * 16;
        b_off = TILEB + (uint32_t)(wn * 32 + (lane & 15)) * ROWB + (lane >> 4) * 16;
        #pragma unroll
        for (int i = 0; i < 4; i++)
            #pragma unroll
            for (int j = 0; j < 4; j++)
                #pragma unroll
                for (int r = 0; r < 4; r++) acc[i][j][r] = 0.0f;
    }

    __device__ __forceinline__ void load_chunk(int kc) {
        const uint32_t st = tiles + (kc & (NSTG - 1)) * STGB;
        const char* ga = Ag + (size_t)kc * (BKC * 2);
        const char* gb = Wg + (size_t)kc * (BKC * 2);
        CP_ASYNC16(st + sw0,              ga);
        CP_ASYNC16(st + sw0 + 16,         ga + 16);
        CP_ASYNC16(st + TILEB + sw0,      gb);
        CP_ASYNC16(st + TILEB + sw0 + 16, gb + 16);
        CP_COMMIT();
    }

    __device__ __forceinline__ void run() {
        load_chunk(0); load_chunk(1); load_chunk(2);
        #pragma unroll 1
        for (int kc = 0; kc < NCHUNK; kc++) {
            if (kc < NCHUNK - 2)       cp_wait<2>();
            else if (kc == NCHUNK - 2) cp_wait<1>();
            else                       cp_wait<0>();
            __syncthreads();
            if (kc + 3 < NCHUNK) load_chunk(kc + 3);

            const uint32_t st = tiles + (kc & (NSTG - 1)) * STGB;
            #pragma unroll
            for (int ks = 0; ks < 2; ks++) {
                const uint32_t kb = ks * 32;
                uint32_t a[4][4], b[2][4];
                #pragma unroll
                for (int mf = 0; mf < 4; mf++)
                    ldsm_x4(a[mf], st + a_off + mf * (16 * ROWB) + kb);
                #pragma unroll
                for (int nf2 = 0; nf2 < 2; nf2++)
                    ldsm_x4(b[nf2], st + b_off + nf2 * (16 * ROWB) + kb);
                #pragma unroll
                for (int mf = 0; mf < 4; mf++) {
                    #pragma unroll
                    for (int nf = 0; nf < 4; nf++)
                        mma_fp16(acc[mf][nf], a[mf],
                                 b[nf >> 1][nf & 1], b[nf >> 1][(nf & 1) + 2]);
                }
            }
        }
    }
};

// ---------------------------------------------------------------------------
// Fused QKV GEMM -> fp16 outputs (seg 0=Q+phi, 1=K+phi, 2=V); grid (24, 128)
// ---------------------------------------------------------------------------
__global__ void __launch_bounds__(256, 2) gemm_qkv(
    const __half* __restrict__ A, const __half* __restrict__ Wqkv,
    const float* __restrict__ bq, const float* __restrict__ bk,
    const float* __restrict__ bv,
    __half* __restrict__ Cq, __half* __restrict__ Ck, __half* __restrict__ Cv)
{
    extern __shared__ char smraw[];
    const int tid = threadIdx.x;
    const int wid = tid >> 5, lane = tid & 31;
    const int wm  = wid >> 2, wn = wid & 3;
    const int bm  = blockIdx.y, bn = blockIdx.x;

    const int seg = bn >> 3;
    const float* bias = seg == 0 ? bq : (seg == 1 ? bk : bv);
    __half* C = seg == 0 ? Cq : (seg == 1 ? Ck : Cv);
    const bool act = seg < 2;

    GemmCore g;
    g.init(smem_u32(smraw), tid, A, Wqkv, bm, bn);
    g.run();

    #pragma unroll
    for (int mf = 0; mf < 4; mf++) {
        const int m0 = bm * 128 + wm * 64 + mf * 16 + (lane >> 2);
        #pragma unroll
        for (int nf = 0; nf < 4; nf++) {
            const int nc = (bn & 7) * 128 + wn * 32 + nf * 8 + (lane & 3) * 2;
            const float b0 = __ldg(bias + nc), b1 = __ldg(bias + nc + 1);
            float l0 = g.acc[mf][nf][0] + b0, l1 = g.acc[mf][nf][1] + b1;
            float h0 = g.acc[mf][nf][2] + b0, h1 = g.acc[mf][nf][3] + b1;
            if (act) { l0 = phi_act(l0); l1 = phi_act(l1);
                       h0 = phi_act(h0); h1 = phi_act(h1); }
            *(__half2*)(C + (size_t)m0 * 1024 + nc) =
                __half2(__float2half(l0), __float2half(l1));
            *(__half2*)(C + (size_t)(m0 + 8) * 1024 + nc) =
                __half2(__float2half(h0), __float2half(h1));
        }
    }
}

// ---------------------------------------------------------------------------
// Output GEMM, 128x64 tile: out = attn_fp16 @ Wo^T + bo -> fp32
// grid (16, 128) = 2048 blocks; 8 warps as 4(M)x2(N), warp tile 32x32.
// ---------------------------------------------------------------------------
__global__ void __launch_bounds__(256, 2) gemm_out(
    const __half* __restrict__ A, const __half* __restrict__ W,
    const float* __restrict__ bias, float* __restrict__ C)
{
    extern __shared__ char smraw[];
    const uint32_t tiles = smem_u32(smraw);
    const int tid = threadIdx.x;
    const int wid = tid >> 5, lane = tid & 31;
    const int wm  = wid >> 1, wn = wid & 1;
    const int bm  = blockIdx.y, bn = blockIdx.x;

    // load geometry: A = 512 segs (2/thread), B = 256 segs (1/thread)
    // seg s: row = s>>2, c16 = s&3
    const int sa0 = tid, sa1 = tid + 256, sb0 = tid;
    const uint32_t a_sm0 = (uint32_t)(sa0 >> 2) * ROWB + (sa0 & 3) * 16;
    const uint32_t a_sm1 = (uint32_t)(sa1 >> 2) * ROWB + (sa1 & 3) * 16;
    const uint32_t b_sm0 = TILEB + (uint32_t)(sb0 >> 2) * ROWB + (sb0 & 3) * 16;
    const char* Ag0 = (const char*)(A + (size_t)(bm * 128 + (sa0 >> 2)) * KK) + (sa0 & 3) * 16;
    const char* Ag1 = (const char*)(A + (size_t)(bm * 128 + (sa1 >> 2)) * KK) + (sa1 & 3) * 16;
    const char* Wg0 = (const char*)(W + (size_t)(bn * 64 + (sb0 >> 2)) * KK) + (sb0 & 3) * 16;

    auto load_chunk = [&](int kc) {
        const uint32_t st = tiles + (kc & (NSTG - 1)) * STGB64;
        const size_t go = (size_t)kc * (BKC * 2);
        CP_ASYNC16(st + a_sm0, Ag0 + go);
        CP_ASYNC16(st + a_sm1, Ag1 + go);
        CP_ASYNC16(st + b_sm0, Wg0 + go);
        CP_COMMIT();
    };

    const uint32_t a_base = (uint32_t)(wm * 32 + (lane & 15)) * ROWB + (lane >> 4) * 16;
    const uint32_t b_base = TILEB + (uint32_t)(wn * 32 + (lane & 15)) * ROWB + (lane >> 4) * 16;

    float acc[2][4][4];
    #pragma unroll
    for (int i = 0; i < 2; i++)
        #pragma unroll
        for (int j = 0; j < 4; j++)
            #pragma unroll
            for (int r = 0; r < 4; r++) acc[i][j][r] = 0.0f;

    load_chunk(0); load_chunk(1); load_chunk(2);

    #pragma unroll 1
    for (int kc = 0; kc < NCHUNK; kc++) {
        if (kc < NCHUNK - 2)       cp_wait<2>();
        else if (kc == NCHUNK - 2) cp_wait<1>();
        else                       cp_wait<0>();
        __syncthreads();
        if (kc + 3 < NCHUNK) load_chunk(kc + 3);

        const uint32_t st = tiles + (kc & (NSTG - 1)) * STGB64;
        #pragma unroll
        for (int ks = 0; ks < 2; ks++) {
            const uint32_t ko = ks * 32;
            uint32_t a[2][4], bl[2][4];
            ldsm_x4(a[0], st + a_base + ko);
            ldsm_x4(a[1], st + a_base + 16 * ROWB + ko);
            ldsm_x4(bl[0], st + b_base + ko);
            ldsm_x4(bl[1], st + b_base + 16 * ROWB + ko);
            #pragma unroll
            for (int mf = 0; mf < 2; mf++)
                #pragma unroll
                for (int nf = 0; nf < 4; nf++)
                    mma_fp16(acc[mf][nf], a[mf],
                             bl[nf >> 1][nf & 1], bl[nf >> 1][(nf & 1) + 2]);
        }
    }

    #pragma unroll
    for (int mf = 0; mf < 2; mf++) {
        const int m0 = bm * 128 + wm * 32 + mf * 16 + (lane >> 2);
        #pragma unroll
        for (int nf = 0; nf < 4; nf++) {
            const int nc = bn * 64 + wn * 32 + nf * 8 + (lane & 3) * 2;
            const float b0 = __ldg(bias + nc), b1 = __ldg(bias + nc + 1);
            float2 lo, hi;
            lo.x = acc[mf][nf][0] + b0; lo.y = acc[mf][nf][1] + b1;
            hi.x = acc[mf][nf][2] + b0; hi.y = acc[mf][nf][3] + b1;
            *(float2*)(C + (size_t)m0 * 1024 + nc)       = lo;
            *(float2*)(C + (size_t)(m0 + 8) * 1024 + nc) = hi;
        }
    }
}

// ---------------------------------------------------------------------------
// All fp32->fp16 conversions in ONE launch, 4 rows/block for MLP=4.
// ---------------------------------------------------------------------------
__global__ __launch_bounds__(256) void conv_all(
    const float* __restrict__ x,  const float* __restrict__ Wq,
    const float* __restrict__ Wk, const float* __restrict__ Wv,
    const float* __restrict__ Wo)
{
    const int r0 = blockIdx.x * 4;
    const float* src;
    __half* dst;
    if (r0 < MT) {
        src = x + (size_t)r0 * 1024;
        dst = g_xs + (size_t)r0 * 1024;
    } else if (r0 < MT + 1024) {
        src = Wq + (size_t)(r0 - MT) * 1024;
        dst = g_wqkv + (size_t)(r0 - MT) * 1024;
    } else if (r0 < MT + 2048) {
        src = Wk + (size_t)(r0 - MT - 1024) * 1024;
        dst = g_wqkv + (size_t)(r0 - MT) * 1024;
    } else if (r0 < MT + 3072) {
        src = Wv + (size_t)(r0 - MT - 2048) * 1024;
        dst = g_wqkv + (size_t)(r0 - MT) * 1024;
    } else {
        src = Wo + (size_t)(r0 - MT - 3072) * 1024;
        dst = g_wos + (size_t)(r0 - MT - 3072) * 1024;
    }
    const int t = threadIdx.x;
    float4 v0 = *(const float4*)(src + (t      ) * 4);
    float4 v1 = *(const float4*)(src + (t + 256) * 4);
    float4 v2 = *(const float4*)(src + (t + 512) * 4);
    float4 v3 = *(const float4*)(src + (t + 768) * 4);
    __half2* d;
    d = (__half2*)(dst + (size_t)t * 4);
    d[0] = __half2(__float2half(v0.x), __float2half(v0.y));
    d[1] = __half2(__float2half(v0.z), __float2half(v0.w));
    d = (__half2*)(dst + (size_t)(t + 256) * 4);
    d[0] = __half2(__float2half(v1.x), __float2half(v1.y));
    d[1] = __half2(__float2half(v1.z), __float2half(v1.w));
    d = (__half2*)(dst + (size_t)(t + 512) * 4);
    d[0] = __half2(__float2half(v2.x), __float2half(v2.y));
    d[1] = __half2(__float2half(v2.z), __float2half(v2.w));
    d = (__half2*)(dst + (size_t)(t + 768) * 4);
    d[0] = __half2(__float2half(v3.x), __float2half(v3.y));
    d[1] = __half2(__float2half(v3.z), __float2half(v3.w));
}

// ---------------------------------------------------------------------------
// KV summary (HMMA): per (b,h,split): kv[64,64] = k^T @ v over 512 t.
// grid (64, 8), 8 warps: 2 (m=dk) x 4 (n=dm). Plain stores to partials.
// ---------------------------------------------------------------------------
__global__ __launch_bounds__(256) void kv_hmma(
    const __half* __restrict__ k16, const __half* __restrict__ v16)
{
    __shared__ __align__(16) char sm[4 * 2 * 32 * RS64];
    const uint32_t smb = smem_u32(sm);
    const int tid = threadIdx.x, lane = tid & 31, wid = tid >> 5;
    const int wm = wid >> 2, wn = wid & 3;
    const int bh = blockIdx.x, b = bh >> 4, h = bh & 15;
    const int spl = blockIdx.y;
    const int t0 = spl * 512;
    static constexpr int NCH = 16;
    static constexpr int STG = 2 * 32 * RS64;

    const int lrow = tid >> 3, lseg = tid & 7;
    const __half* gk = k16 + (size_t)(b * TT + t0 + lrow) * 1024 + h * 64 + lseg * 8;
    const __half* gv = v16 + (size_t)(b * TT + t0 + lrow) * 1024 + h * 64 + lseg * 8;
    const uint32_t sdst = (uint32_t)lrow * RS64 + lseg * 16;

    auto load_chunk = [&](int ch) {
        const uint32_t st = smb + (ch & 3) * STG;
        const size_t go = (size_t)ch * 32 * 1024;
        CP_ASYNC16(st + sdst,             gk + go);
        CP_ASYNC16(st + 32 * RS64 + sdst, gv + go);
        CP_COMMIT();
    };

    const uint32_t trow = (lane & 7) + ((lane >> 4) & 1) * 8;
    const uint32_t tcol = ((lane >> 3) & 1) * 8;
    const uint32_t a_base = trow * RS64 + (wm * 32 + tcol) * 2;
    const uint32_t b_base = 32 * RS64 + trow * RS64 + (wn * 16 + tcol) * 2;

    float acc[2][2][4];
    #pragma unroll
    for (int i = 0; i < 2; i++)
        #pragma unroll
        for (int j = 0; j < 2; j++)
            #pragma unroll
            for (int r = 0; r < 4; r++) acc[i][j][r] = 0.0f;
    float ks0 = 0.0f, ks1 = 0.0f, ks2 = 0.0f, ks3 = 0.0f;

    load_chunk(0); load_chunk(1); load_chunk(2);

    #pragma unroll 1
    for (int ch = 0; ch < NCH; ch++) {
        if (ch < NCH - 2)       cp_wait<2>();
        else if (ch == NCH - 2) cp_wait<1>();
        else                    cp_wait<0>();
        __syncthreads();
        if (ch + 3 < NCH) load_chunk(ch + 3);

        const uint32_t st = smb + (ch & 3) * STG;
        #pragma unroll
        for (int ks = 0; ks < 2; ks++) {
            const uint32_t ko = ks * 16 * RS64;
            uint32_t a[2][4], bfr[4];
            ldsm_x4_t(a[0], st + a_base + ko);
            ldsm_x4_t(a[1], st + a_base + ko + 16 * 2);
            ldsm_x4_t(bfr,  st + b_base + ko);
            #pragma unroll
            for (int mf = 0; mf < 2; mf++)
                #pragma unroll
                for (int nf = 0; nf < 2; nf++)
                    mma_fp16(acc[mf][nf], a[mf], bfr[nf], bfr[nf + 2]);
        }
        // ksum partial with 4-way ILP (warps 0,1 only)
        if (tid < 64) {
            const char* kc = sm + (ch & 3) * STG + tid * 2;
            #pragma unroll
            for (int r = 0; r < 32; r += 4) {
                ks0 += __half2float(*(const __half*)(kc + (r + 0) * RS64));
                ks1 += __half2float(*(const __half*)(kc + (r + 1) * RS64));
                ks2 += __half2float(*(const __half*)(kc + (r + 2) * RS64));
                ks3 += __half2float(*(const __half*)(kc + (r + 3) * RS64));
            }
        }
    }

    float* kvb = g_kvp + ((size_t)bh * NSPL + spl) * (DKK * DKK);
    #pragma unroll
    for (int mf = 0; mf < 2; mf++) {
        const int row = wm * 32 + mf * 16 + (lane >> 2);
        #pragma unroll
        for (int nf = 0; nf < 2; nf++) {
            const int col = wn * 16 + nf * 8 + (lane & 3) * 2;
            *(float2*)&kvb[row * 64 + col] =
                make_float2(acc[mf][nf][0], acc[mf][nf][1]);
            *(float2*)&kvb[(row + 8) * 64 + col] =
                make_float2(acc[mf][nf][2], acc[mf][nf][3]);
        }
    }
    if (tid < 64)
        g_ksp[((size_t)bh * NSPL + spl) * 64 + tid] = (ks0 + ks1) + (ks2 + ks3);
}

// ---------------------------------------------------------------------------
// kv fixup (parallel): grid 1024 = 64 bh x 16 parts, 1 element/thread.
// ---------------------------------------------------------------------------
__global__ __launch_bounds__(256) void kv_fix()
{
    const int bh   = blockIdx.x >> 4;
    const int part = blockIdx.x & 15;
    const float* base = g_kvp + (size_t)bh * NSPL * 4096;
    __half* kvT = g_kvT + (size_t)bh * 4096;

    const int i = part * 256 + threadIdx.x;  // i = dk*64 + dm
    float s = 0.0f;
    #pragma unroll
    for (int p = 0; p < NSPL; p++) s += base[p * 4096 + i];
    const int dk = i >> 6, dm = i & 63;
    kvT[dm * 64 + dk] = __float2half(s);

    if (part == 0 && threadIdx.x < 64) {
        float ks = 0.0f;
        #pragma unroll
        for (int p = 0; p < NSPL; p++)
            ks += g_ksp[((size_t)bh * NSPL + p) * 64 + threadIdx.x];
        g_kse[bh * 64 + threadIdx.x] = ks + EPSV;
    }
}

// ---------------------------------------------------------------------------
// Attention apply (HMMA): out[t,dm] = z[t] * (q[t,:] @ kv[:,dm]), fp16 out.
// grid (64, 32), 8 warps: 4 (m=t) x 2 (n=dm).
// ---------------------------------------------------------------------------
__global__ __launch_bounds__(256) void attn_hmma(
    const __half* __restrict__ q16, __half* __restrict__ out)
{
    __shared__ __align__(16) char smq[128 * RS64];
    __shared__ __align__(16) char smkv[64 * RS64];
    __shared__ float zs[128];
    __shared__ float kse[64];

    const uint32_t sq = smem_u32(smq), skv = smem_u32(smkv);
    const int tid = threadIdx.x, lane = tid & 31, wid = tid >> 5;
    const int wm = wid >> 1, wn = wid & 1;
    const int bh = blockIdx.x, b = bh >> 4, h = bh & 15;
    const int t0 = blockIdx.y * 128;

    {
        const __half* gq = q16 + (size_t)(b * TT + t0) * 1024 + h * 64;
        #pragma unroll
        for (int i = 0; i < 4; i++) {
            const int s = i * 256 + tid;
            const int r = s >> 3, c = s & 7;
            CP_ASYNC16(sq + r * RS64 + c * 16, gq + (size_t)r * 1024 + c * 8);
        }
        const __half* gkv = g_kvT + (size_t)bh * 4096;
        #pragma unroll
        for (int i = 0; i < 2; i++) {
            const int s = i * 256 + tid;
            const int r = s >> 3, c = s & 7;
            CP_ASYNC16(skv + r * RS64 + c * 16, gkv + r * 64 + c * 8);
        }
        CP_COMMIT();
    }
    if (tid < 64) kse[tid] = g_kse[bh * 64 + tid];
    cp_wait<0>();
    __syncthreads();

    if (tid < 128) {
        float s = EPSV;
        const char* qrow = smq + tid * RS64;
        #pragma unroll
        for (int d = 0; d < 64; d++)
            s = fmaf(__half2float(*(const __half*)(qrow + d * 2)), kse[d], s);
        zs[tid] = 1.0f / s;
    }
    __syncthreads();

    const uint32_t a_base = (uint32_t)(wm * 32 + (lane & 15)) * RS64 + (lane >> 4) * 16;
    const uint32_t b_base = (uint32_t)(wn * 32 + (lane & 15)) * RS64 + (lane >> 4) * 16;

    float acc[2][4][4];
    #pragma unroll
    for (int i = 0; i < 2; i++)
        #pragma unroll
        for (int j = 0; j < 4; j++)
            #pragma unroll
            for (int r = 0; r < 4; r++) acc[i][j][r] = 0.0f;

    #pragma unroll
    for (int ks = 0; ks < 4; ks++) {
        const uint32_t ko = ks * 32;
        uint32_t a[2][4], bl[2][4];
        ldsm_x4(a[0], sq + a_base + ko);
        ldsm_x4(a[1], sq + a_base + 16 * RS64 + ko);
        ldsm_x4(bl[0], skv + b_base + ko);
        ldsm_x4(bl[1], skv + b_base + 16 * RS64 + ko);
        #pragma unroll
        for (int mf = 0; mf < 2; mf++)
            #pragma unroll
            for (int nf = 0; nf < 4; nf++)
                mma_fp16(acc[mf][nf], a[mf],
                         bl[nf >> 1][nf & 1], bl[nf >> 1][(nf & 1) + 2]);
    }

    #pragma unroll
    for (int mf = 0; mf < 2; mf++) {
        const int row = wm * 32 + mf * 16 + (lane >> 2);
        const float z0 = zs[row], z1 = zs[row + 8];
        #pragma unroll
        for (int nf = 0; nf < 4; nf++) {
            const int col = wn * 32 + nf * 8 + (lane & 3) * 2;
            __half2* o0 = (__half2*)(out + (size_t)(b * TT + t0 + row) * 1024 + h * 64 + col);
            __half2* o1 = (__half2*)(out + (size_t)(b * TT + t0 + row + 8) * 1024 + h * 64 + col);
            *o0 = __half2(__float2half(acc[mf][nf][0] * z0),
                          __float2half(acc[mf][nf][1] * z0));
            *o1 = __half2(__float2half(acc[mf][nf][2] * z1),
                          __float2half(acc[mf][nf][3] * z1));
        }
    }
}

// ---------------------------------------------------------------------------
extern "C" void kernel_launch(void* const* d_in, const int* in_sizes, int n_in,
                              void* d_out, int out_size)
{
    const float* x  = (const float*)d_in[0];
    const float* Wq = (const float*)d_in[1];
    const float* bq = (const float*)d_in[2];
    const float* Wk = (const float*)d_in[3];
    const float* bk = (const float*)d_in[4];
    const float* Wv = (const float*)d_in[5];
    const float* bv = (const float*)d_in[6];
    const float* Wo = (const float*)d_in[7];
    const float* bo = (const float*)d_in[8];
    float* out = (float*)d_out;

    __half *xs, *as, *wqkv, *wos, *qp, *kp, *vp;
    cudaGetSymbolAddress((void**)&xs,   g_xs);
    cudaGetSymbolAddress((void**)&as,   g_as);
    cudaGetSymbolAddress((void**)&wqkv, g_wqkv);
    cudaGetSymbolAddress((void**)&wos,  g_wos);
    cudaGetSymbolAddress((void**)&qp,   g_q16);
    cudaGetSymbolAddress((void**)&kp,   g_k16);
    cudaGetSymbolAddress((void**)&vp,   g_v16);

    cudaFuncSetAttribute(gemm_qkv, cudaFuncAttributeMaxDynamicSharedMemorySize, SMEM_GEMM);
    cudaFuncSetAttribute(gemm_out, cudaFuncAttributeMaxDynamicSharedMemorySize, SMEM_GEMM64);

    conv_all<<<(MT + 4 * 1024) / 4, 256>>>(x, Wq, Wk, Wv, Wo);

    gemm_qkv<<<dim3(24, MT / 128), 256, SMEM_GEMM>>>(
        xs, wqkv, bq, bk, bv, qp, kp, vp);

    kv_hmma<<<dim3(BB * HH, NSPL), 256>>>(kp, vp);
    kv_fix<<<BB * HH * 16, 256>>>();
    attn_hmma<<<dim3(BB * HH, TT / 128), 256>>>(qp, as);

    gemm_out<<<dim3(DD / 64, MT / 128), 256, SMEM_GEMM64>>>(as, wos, bo, out);
}

// round 13
// speedup vs baseline: 1.1501x; 1.0588x over previous
#include <cuda_runtime.h>
#include <cuda_fp16.h>
#include <math.h>
#include <stdint.h>

// Problem constants
static constexpr int BB  = 4;
static constexpr int TT  = 4096;
static constexpr int DD  = 1024;
static constexpr int HH  = 16;
static constexpr int DKK = 64;
static constexpr int MT  = BB * TT;      // 16384 tokens
static constexpr int KK  = DD;           // fp16 GEMM K = 1024
static constexpr int BKC = 32;           // K-chunk (fp16 elems)
static constexpr int NCHUNK = KK / BKC;  // 32
static constexpr int NSPL = 8;           // kv t-splits
#define EPSV 1e-6f

// GEMM SMEM geometry: rows padded to 40 fp16 (80 B) for conflict-free ldmatrix
static constexpr int ROWB  = 80;
static constexpr int TILEB = 128 * ROWB;      // A tile bytes (128 rows)
static constexpr int NSTG  = 4;

// 128x64 tile geometry (both GEMMs)
static constexpr int TILEB_B64 = 64 * ROWB;            // 5120
static constexpr int STGB64    = TILEB + TILEB_B64;    // 15360
static constexpr int SMEM_GEMM64 = NSTG * STGB64;      // 61440

// kv/attn smem row stride for 64-wide fp16 tiles: 128B data + 16B pad
static constexpr int RS64 = 144;

// ---------------------------------------------------------------------------
// Scratch (device globals — no allocation allowed)
// ---------------------------------------------------------------------------
__device__ __half g_xs[(size_t)MT * KK];      // x fp16
__device__ __half g_as[(size_t)MT * KK];      // attn out fp16
__device__ __half g_wqkv[3 * DD * KK];        // packed Wq|Wk|Wv fp16
__device__ __half g_wos[DD * KK];             // Wo fp16
__device__ __half g_q16[(size_t)MT * DD];
__device__ __half g_k16[(size_t)MT * DD];
__device__ __half g_v16[(size_t)MT * DD];
__device__ float  g_kvp[BB * HH * NSPL * DKK * DKK];  // kv partials (8 MB)
__device__ float  g_ksp[BB * HH * NSPL * DKK];        // ksum partials
__device__ __half g_kvT[BB * HH * DKK * DKK];         // fp16 kv^T
__device__ float  g_kse[BB * HH * DKK];               // ksum + eps
__device__ int    g_cnt[BB * HH];                     // arrival counters (zeroed)

__device__ __forceinline__ float phi_act(float x) {
    return x > 0.0f ? x + 1.0f : expf(x);
}

// ---------------------------------------------------------------------------
// PTX helpers (baseline sm_80+ features only)
// ---------------------------------------------------------------------------
__device__ __forceinline__ uint32_t smem_u32(const void* p) {
    uint32_t a;
    asm("{ .reg .u64 t; cvta.to.shared.u64 t, %1; cvt.u32.u64 %0, t; }"
        : "=r"(a) : "l"(p));
    return a;
}

#define CP_ASYNC16(sm, gp) \
    asm volatile("cp.async.cg.shared.global [%0], [%1], 16;" :: "r"(sm), "l"(gp))
#define CP_COMMIT() asm volatile("cp.async.commit_group;")
template <int N> __device__ __forceinline__ void cp_wait() {
    asm volatile("cp.async.wait_group %0;" :: "n"(N));
}

__device__ __forceinline__ void ldsm_x4(uint32_t* r, uint32_t addr) {
    asm volatile("ldmatrix.sync.aligned.m8n8.x4.shared.b16 {%0,%1,%2,%3}, [%4];"
                 : "=r"(r[0]), "=r"(r[1]), "=r"(r[2]), "=r"(r[3]) : "r"(addr));
}
__device__ __forceinline__ void ldsm_x4_t(uint32_t* r, uint32_t addr) {
    asm volatile("ldmatrix.sync.aligned.m8n8.x4.trans.shared.b16 {%0,%1,%2,%3}, [%4];"
                 : "=r"(r[0]), "=r"(r[1]), "=r"(r[2]), "=r"(r[3]) : "r"(addr));
}

__device__ __forceinline__ void mma_fp16(float* c, const uint32_t* a,
                                         uint32_t b0, uint32_t b1) {
    asm volatile(
        "mma.sync.aligned.m16n8k16.row.col.f32.f16.f16.f32 "
        "{%0,%1,%2,%3}, {%4,%5,%6,%7}, {%8,%9}, {%0,%1,%2,%3};"
        : "+f"(c[0]), "+f"(c[1]), "+f"(c[2]), "+f"(c[3])
        : "r"(a[0]), "r"(a[1]), "r"(a[2]), "r"(a[3]), "r"(b0), "r"(b1));
}

// ---------------------------------------------------------------------------
// 128x64-tile GEMM mainloop (shared by both GEMMs). 8 warps: 4(M)x2(N),
// warp tile 32x32. Produces acc[2][4][4].
// ---------------------------------------------------------------------------
struct Gemm64 {
    uint32_t tiles, a_sm0, a_sm1, b_sm0, a_base, b_base;
    const char *Ag0, *Ag1, *Wg0;
    float acc[2][4][4];

    __device__ __forceinline__ void init(uint32_t tiles_, int tid,
                                         const __half* A, const __half* W,
                                         int am0, int wn0) {
        tiles = tiles_;
        const int wid = tid >> 5, lane = tid & 31;
        const int wm = wid >> 1, wn = wid & 1;
        // loads: A = 512 segs (2/thread), B = 256 segs (1/thread); seg s:
        // row = s>>2, c16 = s&3
        const int sa0 = tid, sa1 = tid + 256;
        a_sm0 = (uint32_t)(sa0 >> 2) * ROWB + (sa0 & 3) * 16;
        a_sm1 = (uint32_t)(sa1 >> 2) * ROWB + (sa1 & 3) * 16;
        b_sm0 = TILEB + (uint32_t)(tid >> 2) * ROWB + (tid & 3) * 16;
        Ag0 = (const char*)(A + (size_t)(am0 + (sa0 >> 2)) * KK) + (sa0 & 3) * 16;
        Ag1 = (const char*)(A + (size_t)(am0 + (sa1 >> 2)) * KK) + (sa1 & 3) * 16;
        Wg0 = (const char*)(W + (size_t)(wn0 + (tid >> 2)) * KK) + (tid & 3) * 16;
        a_base = (uint32_t)(wm * 32 + (lane & 15)) * ROWB + (lane >> 4) * 16;
        b_base = TILEB + (uint32_t)(wn * 32 + (lane & 15)) * ROWB + (lane >> 4) * 16;
        #pragma unroll
        for (int i = 0; i < 2; i++)
            #pragma unroll
            for (int j = 0; j < 4; j++)
                #pragma unroll
                for (int r = 0; r < 4; r++) acc[i][j][r] = 0.0f;
    }

    __device__ __forceinline__ void load_chunk(int kc) {
        const uint32_t st = tiles + (kc & (NSTG - 1)) * STGB64;
        const size_t go = (size_t)kc * (BKC * 2);
        CP_ASYNC16(st + a_sm0, Ag0 + go);
        CP_ASYNC16(st + a_sm1, Ag1 + go);
        CP_ASYNC16(st + b_sm0, Wg0 + go);
        CP_COMMIT();
    }

    __device__ __forceinline__ void run() {
        load_chunk(0); load_chunk(1); load_chunk(2);
        #pragma unroll 1
        for (int kc = 0; kc < NCHUNK; kc++) {
            if (kc < NCHUNK - 2)       cp_wait<2>();
            else if (kc == NCHUNK - 2) cp_wait<1>();
            else                       cp_wait<0>();
            __syncthreads();
            if (kc + 3 < NCHUNK) load_chunk(kc + 3);

            const uint32_t st = tiles + (kc & (NSTG - 1)) * STGB64;
            #pragma unroll
            for (int ks = 0; ks < 2; ks++) {
                const uint32_t ko = ks * 32;
                uint32_t a[2][4], bl[2][4];
                ldsm_x4(a[0], st + a_base + ko);
                ldsm_x4(a[1], st + a_base + 16 * ROWB + ko);
                ldsm_x4(bl[0], st + b_base + ko);
                ldsm_x4(bl[1], st + b_base + 16 * ROWB + ko);
                #pragma unroll
                for (int mf = 0; mf < 2; mf++)
                    #pragma unroll
                    for (int nf = 0; nf < 4; nf++)
                        mma_fp16(acc[mf][nf], a[mf],
                                 bl[nf >> 1][nf & 1], bl[nf >> 1][(nf & 1) + 2]);
            }
        }
    }
};

// ---------------------------------------------------------------------------
// Fused QKV GEMM, 128x64 tiles -> fp16 (seg 0=Q+phi, 1=K+phi, 2=V)
// grid (48, 128) = 6144 blocks.
// ---------------------------------------------------------------------------
__global__ void __launch_bounds__(256, 2) gemm_qkv(
    const __half* __restrict__ A, const __half* __restrict__ Wqkv,
    const float* __restrict__ bq, const float* __restrict__ bk,
    const float* __restrict__ bv,
    __half* __restrict__ Cq, __half* __restrict__ Ck, __half* __restrict__ Cv)
{
    extern __shared__ char smraw[];
    const int tid = threadIdx.x;
    const int wid = tid >> 5, lane = tid & 31;
    const int wm  = wid >> 1, wn = wid & 1;
    const int bm  = blockIdx.y, bn = blockIdx.x;

    const int seg = bn >> 4;                  // 0=q, 1=k, 2=v
    const float* bias = seg == 0 ? bq : (seg == 1 ? bk : bv);
    __half* C = seg == 0 ? Cq : (seg == 1 ? Ck : Cv);
    const bool act = seg < 2;

    Gemm64 g;
    g.init(smem_u32(smraw), tid, A, Wqkv, bm * 128, bn * 64);
    g.run();

    #pragma unroll
    for (int mf = 0; mf < 2; mf++) {
        const int m0 = bm * 128 + wm * 32 + mf * 16 + (lane >> 2);
        #pragma unroll
        for (int nf = 0; nf < 4; nf++) {
            const int nc = (bn & 15) * 64 + wn * 32 + nf * 8 + (lane & 3) * 2;
            const float b0 = __ldg(bias + nc), b1 = __ldg(bias + nc + 1);
            float l0 = g.acc[mf][nf][0] + b0, l1 = g.acc[mf][nf][1] + b1;
            float h0 = g.acc[mf][nf][2] + b0, h1 = g.acc[mf][nf][3] + b1;
            if (act) { l0 = phi_act(l0); l1 = phi_act(l1);
                       h0 = phi_act(h0); h1 = phi_act(h1); }
            *(__half2*)(C + (size_t)m0 * 1024 + nc) =
                __half2(__float2half(l0), __float2half(l1));
            *(__half2*)(C + (size_t)(m0 + 8) * 1024 + nc) =
                __half2(__float2half(h0), __float2half(h1));
        }
    }
}

// ---------------------------------------------------------------------------
// Output GEMM, 128x64 tile: out = attn_fp16 @ Wo^T + bo -> fp32
// grid (16, 128) = 2048 blocks.
// ---------------------------------------------------------------------------
__global__ void __launch_bounds__(256, 2) gemm_out(
    const __half* __restrict__ A, const __half* __restrict__ W,
    const float* __restrict__ bias, float* __restrict__ C)
{
    extern __shared__ char smraw[];
    const int tid = threadIdx.x;
    const int wid = tid >> 5, lane = tid & 31;
    const int wm  = wid >> 1, wn = wid & 1;
    const int bm  = blockIdx.y, bn = blockIdx.x;

    Gemm64 g;
    g.init(smem_u32(smraw), tid, A, W, bm * 128, bn * 64);
    g.run();

    #pragma unroll
    for (int mf = 0; mf < 2; mf++) {
        const int m0 = bm * 128 + wm * 32 + mf * 16 + (lane >> 2);
        #pragma unroll
        for (int nf = 0; nf < 4; nf++) {
            const int nc = bn * 64 + wn * 32 + nf * 8 + (lane & 3) * 2;
            const float b0 = __ldg(bias + nc), b1 = __ldg(bias + nc + 1);
            float2 lo, hi;
            lo.x = g.acc[mf][nf][0] + b0; lo.y = g.acc[mf][nf][1] + b1;
            hi.x = g.acc[mf][nf][2] + b0; hi.y = g.acc[mf][nf][3] + b1;
            *(float2*)(C + (size_t)m0 * 1024 + nc)       = lo;
            *(float2*)(C + (size_t)(m0 + 8) * 1024 + nc) = hi;
        }
    }
}

// ---------------------------------------------------------------------------
// All fp32->fp16 conversions in ONE launch, 4 rows/block for MLP=4.
// ---------------------------------------------------------------------------
__global__ __launch_bounds__(256) void conv_all(
    const float* __restrict__ x,  const float* __restrict__ Wq,
    const float* __restrict__ Wk, const float* __restrict__ Wv,
    const float* __restrict__ Wo)
{
    const int r0 = blockIdx.x * 4;
    const float* src;
    __half* dst;
    if (r0 < MT) {
        src = x + (size_t)r0 * 1024;
        dst = g_xs + (size_t)r0 * 1024;
    } else if (r0 < MT + 1024) {
        src = Wq + (size_t)(r0 - MT) * 1024;
        dst = g_wqkv + (size_t)(r0 - MT) * 1024;
    } else if (r0 < MT + 2048) {
        src = Wk + (size_t)(r0 - MT - 1024) * 1024;
        dst = g_wqkv + (size_t)(r0 - MT) * 1024;
    } else if (r0 < MT + 3072) {
        src = Wv + (size_t)(r0 - MT - 2048) * 1024;
        dst = g_wqkv + (size_t)(r0 - MT) * 1024;
    } else {
        src = Wo + (size_t)(r0 - MT - 3072) * 1024;
        dst = g_wos + (size_t)(r0 - MT - 3072) * 1024;
    }
    const int t = threadIdx.x;
    float4 v0 = *(const float4*)(src + (t      ) * 4);
    float4 v1 = *(const float4*)(src + (t + 256) * 4);
    float4 v2 = *(const float4*)(src + (t + 512) * 4);
    float4 v3 = *(const float4*)(src + (t + 768) * 4);
    __half2* d;
    d = (__half2*)(dst + (size_t)t * 4);
    d[0] = __half2(__float2half(v0.x), __float2half(v0.y));
    d[1] = __half2(__float2half(v0.z), __float2half(v0.w));
    d = (__half2*)(dst + (size_t)(t + 256) * 4);
    d[0] = __half2(__float2half(v1.x), __float2half(v1.y));
    d[1] = __half2(__float2half(v1.z), __float2half(v1.w));
    d = (__half2*)(dst + (size_t)(t + 512) * 4);
    d[0] = __half2(__float2half(v2.x), __float2half(v2.y));
    d[1] = __half2(__float2half(v2.z), __float2half(v2.w));
    d = (__half2*)(dst + (size_t)(t + 768) * 4);
    d[0] = __half2(__float2half(v3.x), __float2half(v3.y));
    d[1] = __half2(__float2half(v3.z), __float2half(v3.w));
}

// ---------------------------------------------------------------------------
// KV summary (HMMA) with FUSED final reduction: per (b,h,split) computes the
// partial kv; the last-arriving block per bh reduces all 8 partials into
// fp16 kv^T and kse (threadfence-reduction pattern; counter self-resets so
// graph replays are deterministic). grid (64, 8).
// ---------------------------------------------------------------------------
__global__ __launch_bounds__(256) void kv_hmma(
    const __half* __restrict__ k16, const __half* __restrict__ v16)
{
    __shared__ __align__(16) char sm[4 * 2 * 32 * RS64];
    __shared__ bool is_last;
    const uint32_t smb = smem_u32(sm);
    const int tid = threadIdx.x, lane = tid & 31, wid = tid >> 5;
    const int wm = wid >> 2, wn = wid & 3;
    const int bh = blockIdx.x, b = bh >> 4, h = bh & 15;
    const int spl = blockIdx.y;
    const int t0 = spl * 512;
    static constexpr int NCH = 16;
    static constexpr int STG = 2 * 32 * RS64;

    const int lrow = tid >> 3, lseg = tid & 7;
    const __half* gk = k16 + (size_t)(b * TT + t0 + lrow) * 1024 + h * 64 + lseg * 8;
    const __half* gv = v16 + (size_t)(b * TT + t0 + lrow) * 1024 + h * 64 + lseg * 8;
    const uint32_t sdst = (uint32_t)lrow * RS64 + lseg * 16;

    auto load_chunk = [&](int ch) {
        const uint32_t st = smb + (ch & 3) * STG;
        const size_t go = (size_t)ch * 32 * 1024;
        CP_ASYNC16(st + sdst,             gk + go);
        CP_ASYNC16(st + 32 * RS64 + sdst, gv + go);
        CP_COMMIT();
    };

    const uint32_t trow = (lane & 7) + ((lane >> 4) & 1) * 8;
    const uint32_t tcol = ((lane >> 3) & 1) * 8;
    const uint32_t a_base = trow * RS64 + (wm * 32 + tcol) * 2;
    const uint32_t b_base = 32 * RS64 + trow * RS64 + (wn * 16 + tcol) * 2;

    float acc[2][2][4];
    #pragma unroll
    for (int i = 0; i < 2; i++)
        #pragma unroll
        for (int j = 0; j < 2; j++)
            #pragma unroll
            for (int r = 0; r < 4; r++) acc[i][j][r] = 0.0f;
    float ks0 = 0.0f, ks1 = 0.0f, ks2 = 0.0f, ks3 = 0.0f;

    load_chunk(0); load_chunk(1); load_chunk(2);

    #pragma unroll 1
    for (int ch = 0; ch < NCH; ch++) {
        if (ch < NCH - 2)       cp_wait<2>();
        else if (ch == NCH - 2) cp_wait<1>();
        else                    cp_wait<0>();
        __syncthreads();
        if (ch + 3 < NCH) load_chunk(ch + 3);

        const uint32_t st = smb + (ch & 3) * STG;
        #pragma unroll
        for (int ks = 0; ks < 2; ks++) {
            const uint32_t ko = ks * 16 * RS64;
            uint32_t a[2][4], bfr[4];
            ldsm_x4_t(a[0], st + a_base + ko);
            ldsm_x4_t(a[1], st + a_base + ko + 16 * 2);
            ldsm_x4_t(bfr,  st + b_base + ko);
            #pragma unroll
            for (int mf = 0; mf < 2; mf++)
                #pragma unroll
                for (int nf = 0; nf < 2; nf++)
                    mma_fp16(acc[mf][nf], a[mf], bfr[nf], bfr[nf + 2]);
        }
        if (tid < 64) {
            const char* kc = sm + (ch & 3) * STG + tid * 2;
            #pragma unroll
            for (int r = 0; r < 32; r += 4) {
                ks0 += __half2float(*(const __half*)(kc + (r + 0) * RS64));
                ks1 += __half2float(*(const __half*)(kc + (r + 1) * RS64));
                ks2 += __half2float(*(const __half*)(kc + (r + 2) * RS64));
                ks3 += __half2float(*(const __half*)(kc + (r + 3) * RS64));
            }
        }
    }

    float* kvb = g_kvp + ((size_t)bh * NSPL + spl) * (DKK * DKK);
    #pragma unroll
    for (int mf = 0; mf < 2; mf++) {
        const int row = wm * 32 + mf * 16 + (lane >> 2);
        #pragma unroll
        for (int nf = 0; nf < 2; nf++) {
            const int col = wn * 16 + nf * 8 + (lane & 3) * 2;
            *(float2*)&kvb[row * 64 + col] =
                make_float2(acc[mf][nf][0], acc[mf][nf][1]);
            *(float2*)&kvb[(row + 8) * 64 + col] =
                make_float2(acc[mf][nf][2], acc[mf][nf][3]);
        }
    }
    if (tid < 64)
        g_ksp[((size_t)bh * NSPL + spl) * 64 + tid] = (ks0 + ks1) + (ks2 + ks3);

    // ---- fused reduction: last block per bh sums the 8 partials ----
    __threadfence();
    if (tid == 0)
        is_last = (atomicAdd(&g_cnt[bh], 1) == NSPL - 1);
    __syncthreads();
    if (!is_last) return;

    const float* base = g_kvp + (size_t)bh * NSPL * 4096;
    __half* kvT = g_kvT + (size_t)bh * 4096;
    #pragma unroll
    for (int u = 0; u < 16; u++) {
        const int i = u * 256 + tid;      // i = dk*64 + dm
        float s = 0.0f;
        #pragma unroll
        for (int p = 0; p < NSPL; p++) s += base[p * 4096 + i];
        const int dk = i >> 6, dm = i & 63;
        kvT[dm * 64 + dk] = __float2half(s);
    }
    if (tid < 64) {
        float ks = 0.0f;
        #pragma unroll
        for (int p = 0; p < NSPL; p++)
            ks += g_ksp[((size_t)bh * NSPL + p) * 64 + tid];
        g_kse[bh * 64 + tid] = ks + EPSV;
    }
    if (tid == 0) g_cnt[bh] = 0;          // reset for next graph replay
}

// ---------------------------------------------------------------------------
// Attention apply (HMMA): out[t,dm] = z[t] * (q[t,:] @ kv[:,dm]), fp16 out.
// grid (64, 32), 8 warps: 4 (m=t) x 2 (n=dm).
// ---------------------------------------------------------------------------
__global__ __launch_bounds__(256) void attn_hmma(
    const __half* __restrict__ q16, __half* __restrict__ out)
{
    __shared__ __align__(16) char smq[128 * RS64];
    __shared__ __align__(16) char smkv[64 * RS64];
    __shared__ float zs[128];
    __shared__ float kse[64];

    const uint32_t sq = smem_u32(smq), skv = smem_u32(smkv);
    const int tid = threadIdx.x, lane = tid & 31, wid = tid >> 5;
    const int wm = wid >> 1, wn = wid & 1;
    const int bh = blockIdx.x, b = bh >> 4, h = bh & 15;
    const int t0 = blockIdx.y * 128;

    {
        const __half* gq = q16 + (size_t)(b * TT + t0) * 1024 + h * 64;
        #pragma unroll
        for (int i = 0; i < 4; i++) {
            const int s = i * 256 + tid;
            const int r = s >> 3, c = s & 7;
            CP_ASYNC16(sq + r * RS64 + c * 16, gq + (size_t)r * 1024 + c * 8);
        }
        const __half* gkv = g_kvT + (size_t)bh * 4096;
        #pragma unroll
        for (int i = 0; i < 2; i++) {
            const int s = i * 256 + tid;
            const int r = s >> 3, c = s & 7;
            CP_ASYNC16(skv + r * RS64 + c * 16, gkv + r * 64 + c * 8);
        }
        CP_COMMIT();
    }
    if (tid < 64) kse[tid] = g_kse[bh * 64 + tid];
    cp_wait<0>();
    __syncthreads();

    if (tid < 128) {
        float s = EPSV;
        const char* qrow = smq + tid * RS64;
        #pragma unroll
        for (int d = 0; d < 64; d++)
            s = fmaf(__half2float(*(const __half*)(qrow + d * 2)), kse[d], s);
        zs[tid] = 1.0f / s;
    }
    __syncthreads();

    const uint32_t a_base = (uint32_t)(wm * 32 + (lane & 15)) * RS64 + (lane >> 4) * 16;
    const uint32_t b_base = (uint32_t)(wn * 32 + (lane & 15)) * RS64 + (lane >> 4) * 16;

    float acc[2][4][4];
    #pragma unroll
    for (int i = 0; i < 2; i++)
        #pragma unroll
        for (int j = 0; j < 4; j++)
            #pragma unroll
            for (int r = 0; r < 4; r++) acc[i][j][r] = 0.0f;

    #pragma unroll
    for (int ks = 0; ks < 4; ks++) {
        const uint32_t ko = ks * 32;
        uint32_t a[2][4], bl[2][4];
        ldsm_x4(a[0], sq + a_base + ko);
        ldsm_x4(a[1], sq + a_base + 16 * RS64 + ko);
        ldsm_x4(bl[0], skv + b_base + ko);
        ldsm_x4(bl[1], skv + b_base + 16 * RS64 + ko);
        #pragma unroll
        for (int mf = 0; mf < 2; mf++)
            #pragma unroll
            for (int nf = 0; nf < 4; nf++)
                mma_fp16(acc[mf][nf], a[mf],
                         bl[nf >> 1][nf & 1], bl[nf >> 1][(nf & 1) + 2]);
    }

    #pragma unroll
    for (int mf = 0; mf < 2; mf++) {
        const int row = wm * 32 + mf * 16 + (lane >> 2);
        const float z0 = zs[row], z1 = zs[row + 8];
        #pragma unroll
        for (int nf = 0; nf < 4; nf++) {
            const int col = wn * 32 + nf * 8 + (lane & 3) * 2;
            __half2* o0 = (__half2*)(out + (size_t)(b * TT + t0 + row) * 1024 + h * 64 + col);
            __half2* o1 = (__half2*)(out + (size_t)(b * TT + t0 + row + 8) * 1024 + h * 64 + col);
            *o0 = __half2(__float2half(acc[mf][nf][0] * z0),
                          __float2half(acc[mf][nf][1] * z0));
            *o1 = __half2(__float2half(acc[mf][nf][2] * z1),
                          __float2half(acc[mf][nf][3] * z1));
        }
    }
}

// ---------------------------------------------------------------------------
extern "C" void kernel_launch(void* const* d_in, const int* in_sizes, int n_in,
                              void* d_out, int out_size)
{
    const float* x  = (const float*)d_in[0];
    const float* Wq = (const float*)d_in[1];
    const float* bq = (const float*)d_in[2];
    const float* Wk = (const float*)d_in[3];
    const float* bk = (const float*)d_in[4];
    const float* Wv = (const float*)d_in[5];
    const float* bv = (const float*)d_in[6];
    const float* Wo = (const float*)d_in[7];
    const float* bo = (const float*)d_in[8];
    float* out = (float*)d_out;

    __half *xs, *as, *wqkv, *wos, *qp, *kp, *vp;
    cudaGetSymbolAddress((void**)&xs,   g_xs);
    cudaGetSymbolAddress((void**)&as,   g_as);
    cudaGetSymbolAddress((void**)&wqkv, g_wqkv);
    cudaGetSymbolAddress((void**)&wos,  g_wos);
    cudaGetSymbolAddress((void**)&qp,   g_q16);
    cudaGetSymbolAddress((void**)&kp,   g_k16);
    cudaGetSymbolAddress((void**)&vp,   g_v16);

    cudaFuncSetAttribute(gemm_qkv, cudaFuncAttributeMaxDynamicSharedMemorySize, SMEM_GEMM64);
    cudaFuncSetAttribute(gemm_out, cudaFuncAttributeMaxDynamicSharedMemorySize, SMEM_GEMM64);

    conv_all<<<(MT + 4 * 1024) / 4, 256>>>(x, Wq, Wk, Wv, Wo);

    gemm_qkv<<<dim3(48, MT / 128), 256, SMEM_GEMM64>>>(
        xs, wqkv, bq, bk, bv, qp, kp, vp);

    kv_hmma<<<dim3(BB * HH, NSPL), 256>>>(kp, vp);
    attn_hmma<<<dim3(BB * HH, TT / 128), 256>>>(qp, as);

    gemm_out<<<dim3(DD / 64, MT / 128), 256, SMEM_GEMM64>>>(as, wos, bo, out);
}